// round 1
// baseline (speedup 1.0000x reference)
#include <cuda_runtime.h>
#include <cstdint>

#define MAXN 100352

// Scratch for y = x @ w03 + b03  (gathered per (n,k) later)
__device__ float g_y[MAXN * 64];

// ---------------------------------------------------------------------------
// Kernel A: y[n][c] = b03[c] + sum_d x[n][d] * w03[d][c]
// ---------------------------------------------------------------------------
__global__ void __launch_bounds__(256) gemm_y_kernel(
    const float* __restrict__ x, const float* __restrict__ w03,
    const float* __restrict__ b03, int n)
{
    __shared__ float sw[64 * 64];
    __shared__ float sx[16][64];
    const int tid = threadIdx.x;
    for (int i = tid; i < 4096; i += 256) sw[i] = w03[i];
    const int base = blockIdx.x * 16;
    const int c = tid & 63;
    const int rq = tid >> 6;  // 0..3
#pragma unroll
    for (int a = 0; a < 4; a++) {
        int r = rq * 4 + a;
        int row = base + r;
        sx[r][c] = (row < n) ? x[(size_t)row * 64 + c] : 0.f;
    }
    __syncthreads();
    const float bc = b03[c];
#pragma unroll
    for (int a = 0; a < 4; a++) {
        int r = rq + a * 4;
        int row = base + r;
        if (row < n) {
            float acc = bc;
#pragma unroll
            for (int d = 0; d < 64; d++) acc += sx[r][d] * sw[d * 64 + c];
            g_y[(size_t)row * 64 + c] = acc;
        }
    }
}

// ---------------------------------------------------------------------------
// Kernel B: full fused PointMixer intra-set layer. One block per point n,
// 16 threads per neighbor k (256 threads).
// ---------------------------------------------------------------------------
__global__ void __launch_bounds__(256) pm_main_kernel(
    const float* __restrict__ p, const float* __restrict__ x,
    const int* __restrict__ knn,
    const float* __restrict__ w01, const float* __restrict__ b01,
    const float* __restrict__ blW, const float* __restrict__ blB,
    const float* __restrict__ lp1w, const float* __restrict__ lp1b,
    const float* __restrict__ bnpg, const float* __restrict__ bnpb,
    const float* __restrict__ bnpm, const float* __restrict__ bnpv,
    const float* __restrict__ lp2w, const float* __restrict__ lp2b,
    const float* __restrict__ c2aw,
    const float* __restrict__ bn2ag, const float* __restrict__ bn2ab,
    const float* __restrict__ bn2am, const float* __restrict__ bn2av,
    const float* __restrict__ c2bw,
    const float* __restrict__ bn2bg, const float* __restrict__ bn2bb,
    const float* __restrict__ bn2bm, const float* __restrict__ bn2bv,
    const float* __restrict__ c2cw, const float* __restrict__ c2cb,
    float* __restrict__ out, float* __restrict__ xk_out,
    float* __restrict__ knn_out, float* __restrict__ pr_out,
    int n)
{
    // ---- weights in smem (BN folded) ----
    __shared__ float s_w01[67 * 16];
    __shared__ float s_b01[16];
    __shared__ float s_blW[4096];           // layout [(i*16+j)*16 + o]
    __shared__ float s_blB[16];
    __shared__ float s_lp1[9], s_lp1b[3], s_bnps[3], s_bnpt[3];
    __shared__ float s_lp2[192], s_lp2b[64];
    __shared__ float s_c2a[2048];
    __shared__ float s_bn2as[64], s_bn2at[64];
    __shared__ float s_c2b[512];
    __shared__ float s_bn2bs[8], s_bn2bt[8];
    __shared__ float s_c2c[64], s_c2cb[8];
    // ---- per-k scratch (reused across stages) ----
    __shared__ __align__(16) float s_buf[16 * 64];  // x[j] -> h2a
    __shared__ float s_h[16 * 17];                  // h -> h2b
    __shared__ __align__(16) float s_pe[16 * 64];   // p_embed (kept)
    __shared__ float s_e[16 * 33];                  // [energy|shrink] -> psum
    __shared__ float s_logit[16 * 8];
    __shared__ float s_wsm[16 * 8];
    __shared__ float s_pr[16 * 4];
    __shared__ float s_outv[64];

    const int tid = threadIdx.x;
    const int k = tid >> 4;
    const int t = tid & 15;
    const int nn = blockIdx.x;

    // cooperative weight loads
    for (int i = tid; i < 67 * 16; i += 256) s_w01[i] = w01[i];
    for (int i = tid; i < 4096; i += 256) {
        int o = i >> 8;
        int r = i & 255;
        s_blW[r * 16 + o] = blW[i];
    }
    for (int i = tid; i < 2048; i += 256) s_c2a[i] = c2aw[i];
    for (int i = tid; i < 512; i += 256) s_c2b[i] = c2bw[i];
    if (tid < 192) s_lp2[tid] = lp2w[tid];
    if (tid < 16) { s_b01[tid] = b01[tid]; s_blB[tid] = blB[tid]; }
    if (tid < 9) s_lp1[tid] = lp1w[tid];
    if (tid < 3) {
        s_lp1b[tid] = lp1b[tid];
        float sc = bnpg[tid] * rsqrtf(bnpv[tid] + 1e-5f);
        s_bnps[tid] = sc;
        s_bnpt[tid] = bnpb[tid] - bnpm[tid] * sc;
    }
    if (tid < 64) {
        s_lp2b[tid] = lp2b[tid];
        float sc = bn2ag[tid] * rsqrtf(bn2av[tid] + 1e-5f);
        s_bn2as[tid] = sc;
        s_bn2at[tid] = bn2ab[tid] - bn2am[tid] * sc;
        s_c2c[tid] = c2cw[tid];
        s_outv[tid] = 0.f;
    }
    if (tid < 8) {
        float sc = bn2bg[tid] * rsqrtf(bn2bv[tid] + 1e-5f);
        s_bn2bs[tid] = sc;
        s_bn2bt[tid] = bn2bb[tid] - bn2bm[tid] * sc;
        s_c2cb[tid] = c2cb[tid];
    }

    // ---- gather: knn index, relative coords, x[j] staged ----
    const int j = knn[nn * 16 + k];
    if (t < 3) {
        float v = p[(size_t)j * 3 + t] - p[(size_t)nn * 3 + t];
        s_pr[k * 4 + t] = v;
        if (pr_out) pr_out[((size_t)nn * 16 + k) * 3 + t] = v;
    }
    {
        const float4 xv = *(const float4*)(x + (size_t)j * 64 + t * 4);
        *(float4*)(s_buf + k * 64 + t * 4) = xv;
    }
    if (knn_out && tid < 16)
        knn_out[(size_t)nn * 16 + tid] = (float)knn[nn * 16 + tid];
    __syncthreads();

    // ---- h = relu([p_r, x_j] @ w01 + b01) ; thread t computes h[t] ----
    {
        float acc = s_b01[t];
        acc += s_pr[k * 4 + 0] * s_w01[0 * 16 + t];
        acc += s_pr[k * 4 + 1] * s_w01[1 * 16 + t];
        acc += s_pr[k * 4 + 2] * s_w01[2 * 16 + t];
        const float* xj = s_buf + k * 64;
#pragma unroll
        for (int c = 0; c < 64; c++) acc += xj[c] * s_w01[(3 + c) * 16 + t];
        s_h[k * 17 + t] = fmaxf(acc, 0.f);
    }
    __syncwarp();

    // ---- energy[o=t] = b + h^T blW[o] h ----
    {
        float hreg[16];
#pragma unroll
        for (int i = 0; i < 16; i++) hreg[i] = s_h[k * 17 + i];
        float acc = s_blB[t];
#pragma unroll
        for (int i = 0; i < 16; i++) {
            float s = 0.f;
#pragma unroll
            for (int jj = 0; jj < 16; jj++)
                s += s_blW[(i * 16 + jj) * 16 + t] * hreg[jj];
            acc += hreg[i] * s;
        }
        s_e[k * 33 + t] = acc;
    }

    // ---- p_embed = relu(BN(p_r @ lp1 + b)) @ lp2 + lp2_b ----
    {
        const float pr0 = s_pr[k * 4 + 0], pr1 = s_pr[k * 4 + 1], pr2 = s_pr[k * 4 + 2];
        float q[3];
#pragma unroll
        for (int d = 0; d < 3; d++) {
            float pe = pr0 * s_lp1[0 * 3 + d] + pr1 * s_lp1[1 * 3 + d] +
                       pr2 * s_lp1[2 * 3 + d] + s_lp1b[d];
            q[d] = fmaxf(pe * s_bnps[d] + s_bnpt[d], 0.f);
        }
#pragma unroll
        for (int a = 0; a < 4; a++) {
            int c = t + 16 * a;
            float v = s_lp2b[c] + q[0] * s_lp2[c] + q[1] * s_lp2[64 + c] +
                      q[2] * s_lp2[128 + c];
            s_pe[k * 64 + c] = v;
        }
    }
    __syncwarp();

    // ---- shrink: e[16+t] = sum_a p_embed[a*16+t] ----
    s_e[k * 33 + 16 + t] = s_pe[k * 64 + t] + s_pe[k * 64 + 16 + t] +
                           s_pe[k * 64 + 32 + t] + s_pe[k * 64 + 48 + t];
    __syncwarp();

    // ---- h2a = relu(BN(e @ c2a)) ; thread t -> channels t+16a ----
    {
        float a0 = 0.f, a1 = 0.f, a2 = 0.f, a3 = 0.f;
#pragma unroll
        for (int ei = 0; ei < 32; ei++) {
            float ev = s_e[k * 33 + ei];
            a0 += ev * s_c2a[ei * 64 + t];
            a1 += ev * s_c2a[ei * 64 + t + 16];
            a2 += ev * s_c2a[ei * 64 + t + 32];
            a3 += ev * s_c2a[ei * 64 + t + 48];
        }
        s_buf[k * 64 + t]      = fmaxf(a0 * s_bn2as[t]      + s_bn2at[t], 0.f);
        s_buf[k * 64 + t + 16] = fmaxf(a1 * s_bn2as[t + 16] + s_bn2at[t + 16], 0.f);
        s_buf[k * 64 + t + 32] = fmaxf(a2 * s_bn2as[t + 32] + s_bn2at[t + 32], 0.f);
        s_buf[k * 64 + t + 48] = fmaxf(a3 * s_bn2as[t + 48] + s_bn2at[t + 48], 0.f);
    }
    __syncwarp();

    // ---- h2b = relu(BN(h2a @ c2b)) (8 ch), logits = h2b @ c2c + b ----
    if (t < 8) {
        float acc = 0.f;
#pragma unroll
        for (int c = 0; c < 64; c++) acc += s_buf[k * 64 + c] * s_c2b[c * 8 + t];
        s_h[k * 17 + t] = fmaxf(acc * s_bn2bs[t] + s_bn2bt[t], 0.f);
    }
    __syncwarp();
    if (t < 8) {
        float acc = s_c2cb[t];
#pragma unroll
        for (int u = 0; u < 8; u++) acc += s_h[k * 17 + u] * s_c2c[u * 8 + t];
        s_logit[k * 8 + t] = acc;
    }
    __syncthreads();

    // ---- softmax over the 16 neighbors, per channel c8 ----
    if (tid < 8) {
        float m = -1e30f;
#pragma unroll
        for (int kk = 0; kk < 16; kk++) m = fmaxf(m, s_logit[kk * 8 + tid]);
        float sum = 0.f;
#pragma unroll
        for (int kk = 0; kk < 16; kk++) sum += __expf(s_logit[kk * 8 + tid] - m);
        float inv = 1.f / sum;
#pragma unroll
        for (int kk = 0; kk < 16; kk++)
            s_wsm[kk * 8 + tid] = __expf(s_logit[kk * 8 + tid] - m) * inv;
    }
    __syncthreads();  // also retires all s_e readers; s_e reused as psum below

    // ---- final: xk = (y[j] + p_embed) * w ; out = sum_k xk ----
    {
        const float wv = s_wsm[k * 8 + (t & 7)];
        const float* yrow = g_y + (size_t)j * 64;
        const int warp = tid >> 5;        // 8 warps
        float* psum = s_e;                // reuse (512 of 528 floats)
        float v[4];
#pragma unroll
        for (int a = 0; a < 4; a++) {
            int c = t + 16 * a;
            v[a] = (yrow[c] + s_pe[k * 64 + c]) * wv;
            if (xk_out) xk_out[((size_t)nn * 16 + k) * 64 + c] = v[a];
        }
        // deterministic reduction: pair k-groups within warp, then 8 warps
#pragma unroll
        for (int a = 0; a < 4; a++)
            v[a] += __shfl_down_sync(0xffffffffu, v[a], 16);
        if ((tid & 31) < 16) {
#pragma unroll
            for (int a = 0; a < 4; a++) psum[warp * 64 + t + 16 * a] = v[a];
        }
    }
    __syncthreads();
    if (tid < 64) {
        float acc = 0.f;
#pragma unroll
        for (int w = 0; w < 8; w++) acc += s_e[w * 64 + tid];
        out[(size_t)nn * 64 + tid] = acc;
    }
}

// ---------------------------------------------------------------------------
extern "C" void kernel_launch(void* const* d_in, const int* in_sizes, int n_in,
                              void* d_out, int out_size)
{
    const float* p    = (const float*)d_in[0];
    const float* x    = (const float*)d_in[1];
    const int*   knn  = (const int*)d_in[2];
    const float* w01  = (const float*)d_in[3];
    const float* b01  = (const float*)d_in[4];
    const float* blW  = (const float*)d_in[5];
    const float* blB  = (const float*)d_in[6];
    const float* lp1w = (const float*)d_in[7];
    const float* lp1b = (const float*)d_in[8];
    const float* bnpg = (const float*)d_in[9];
    const float* bnpb = (const float*)d_in[10];
    const float* bnpm = (const float*)d_in[11];
    const float* bnpv = (const float*)d_in[12];
    const float* lp2w = (const float*)d_in[13];
    const float* lp2b = (const float*)d_in[14];
    const float* c2aw = (const float*)d_in[15];
    const float* bn2ag = (const float*)d_in[16];
    const float* bn2ab = (const float*)d_in[17];
    const float* bn2am = (const float*)d_in[18];
    const float* bn2av = (const float*)d_in[19];
    const float* c2bw  = (const float*)d_in[20];
    const float* bn2bg = (const float*)d_in[21];
    const float* bn2bb = (const float*)d_in[22];
    const float* bn2bm = (const float*)d_in[23];
    const float* bn2bv = (const float*)d_in[24];
    const float* c2cw  = (const float*)d_in[25];
    const float* c2cb  = (const float*)d_in[26];
    const float* w03   = (const float*)d_in[27];
    const float* b03   = (const float*)d_in[28];

    const int n = in_sizes[0] / 3;  // p is [n,3]
    float* out = (float*)d_out;

    // Output layout assumption: flattened concat of (out, xk, knn_idx, p_r).
    const long long total = (long long)n * 64 + (long long)n * 16 * 64 +
                            (long long)n * 16 + (long long)n * 16 * 3;
    float* xk_out = nullptr;
    float* knn_out = nullptr;
    float* pr_out = nullptr;
    if ((long long)out_size >= total) {
        xk_out  = out + (size_t)n * 64;
        knn_out = xk_out + (size_t)n * 16 * 64;
        pr_out  = knn_out + (size_t)n * 16;
    }

    gemm_y_kernel<<<(n + 15) / 16, 256>>>(x, w03, b03, n);
    pm_main_kernel<<<n, 256>>>(p, x, knn, w01, b01, blW, blB, lp1w, lp1b,
                               bnpg, bnpb, bnpm, bnpv, lp2w, lp2b,
                               c2aw, bn2ag, bn2ab, bn2am, bn2av,
                               c2bw, bn2bg, bn2bb, bn2bm, bn2bv,
                               c2cw, c2cb,
                               out, xk_out, knn_out, pr_out, n);
}

// round 2
// speedup vs baseline: 2.2998x; 2.2998x over previous
#include <cuda_runtime.h>
#include <cstdint>

#define MAXN 100352

// Scratch for y = x @ w03 + b03
__device__ float g_y[MAXN * 64];

// ---------------------------------------------------------------------------
// Kernel A: y[n][c] = b03[c] + sum_d x[n][d] * w03[d][c]
// ---------------------------------------------------------------------------
__global__ void __launch_bounds__(256) gemm_y_kernel(
    const float* __restrict__ x, const float* __restrict__ w03,
    const float* __restrict__ b03, int n)
{
    __shared__ float sw[64 * 64];
    __shared__ float sx[16][64];
    const int tid = threadIdx.x;
    for (int i = tid; i < 4096; i += 256) sw[i] = w03[i];
    const int base = blockIdx.x * 16;
    const int c = tid & 63;
    const int rq = tid >> 6;
#pragma unroll
    for (int a = 0; a < 4; a++) {
        int r = rq * 4 + a;
        int row = base + r;
        sx[r][c] = (row < n) ? x[(size_t)row * 64 + c] : 0.f;
    }
    __syncthreads();
    const float bc = b03[c];
#pragma unroll
    for (int a = 0; a < 4; a++) {
        int r = rq + a * 4;
        int row = base + r;
        if (row < n) {
            float acc = bc;
#pragma unroll
            for (int d = 0; d < 64; d++) acc += sx[r][d] * sw[d * 64 + c];
            g_y[(size_t)row * 64 + c] = acc;
        }
    }
}

// ---------------------------------------------------------------------------
// Kernel B: one THREAD per (n,k) pair. 192 threads = 12 points per block.
// All weight reads are warp-uniform broadcast LDS.128.
// ---------------------------------------------------------------------------
__global__ void __launch_bounds__(192, 2) pm_main_kernel(
    const float* __restrict__ p, const float* __restrict__ x,
    const int* __restrict__ knn,
    const float* __restrict__ w01, const float* __restrict__ b01,
    const float* __restrict__ blW, const float* __restrict__ blB,
    const float* __restrict__ lp1w, const float* __restrict__ lp1b,
    const float* __restrict__ bnpg, const float* __restrict__ bnpb,
    const float* __restrict__ bnpm, const float* __restrict__ bnpv,
    const float* __restrict__ lp2w, const float* __restrict__ lp2b,
    const float* __restrict__ c2aw,
    const float* __restrict__ bn2ag, const float* __restrict__ bn2ab,
    const float* __restrict__ bn2am, const float* __restrict__ bn2av,
    const float* __restrict__ c2bw,
    const float* __restrict__ bn2bg, const float* __restrict__ bn2bb,
    const float* __restrict__ bn2bm, const float* __restrict__ bn2bv,
    const float* __restrict__ c2cw, const float* __restrict__ c2cb,
    float* __restrict__ out, float* __restrict__ xk_out,
    float* __restrict__ knn_out, float* __restrict__ pr_out,
    int n)
{
    __shared__ __align__(16) float s_w01[1072];   // [c][o], o fastest
    __shared__ __align__(16) float s_blW[4096];   // [o][i][j]
    __shared__ __align__(16) float s_c2a[2048];   // [ei][c]
    __shared__ __align__(16) float s_c2b[512];    // [c][o8]
    __shared__ __align__(16) float s_lp2[192];    // [r][c]
    __shared__ __align__(16) float s_lp2b[64];
    __shared__ __align__(16) float s_bn2as[64], s_bn2at[64];
    __shared__ __align__(16) float s_c2c[64];     // [u][o8]
    __shared__ __align__(16) float s_b01[16], s_blB[16];
    __shared__ __align__(16) float s_lp1f[12], s_lp1c[4];
    __shared__ __align__(16) float s_bn2bs[8], s_bn2bt[8], s_c2cb[8];
    __shared__ float s_h[192 * 17];               // per-thread h scratch

    const int tid = threadIdx.x;

    // ---- stage weights (BN folded) ----
    for (int i = tid; i < 1072; i += 192) s_w01[i] = w01[i];
    for (int i = tid; i < 4096; i += 192) s_blW[i] = blW[i];
    for (int i = tid; i < 2048; i += 192) s_c2a[i] = c2aw[i];
    for (int i = tid; i < 512; i += 192) s_c2b[i] = c2bw[i];
    if (tid < 192) s_lp2[tid] = lp2w[tid];
    if (tid < 64) {
        s_lp2b[tid] = lp2b[tid];
        float sc = bn2ag[tid] * rsqrtf(bn2av[tid] + 1e-5f);
        s_bn2as[tid] = sc;
        s_bn2at[tid] = bn2ab[tid] - bn2am[tid] * sc;
        s_c2c[tid] = c2cw[tid];
    }
    if (tid < 16) { s_b01[tid] = b01[tid]; s_blB[tid] = blB[tid]; }
    if (tid < 8) {
        float sc = bn2bg[tid] * rsqrtf(bn2bv[tid] + 1e-5f);
        s_bn2bs[tid] = sc;
        s_bn2bt[tid] = bn2bb[tid] - bn2bm[tid] * sc;
        s_c2cb[tid] = c2cb[tid];
    }
    if (tid < 3) {
        const int d = tid;
        float sc = bnpg[d] * rsqrtf(bnpv[d] + 1e-5f);
        s_lp1f[0 + d] = lp1w[0 * 3 + d] * sc;
        s_lp1f[4 + d] = lp1w[1 * 3 + d] * sc;
        s_lp1f[8 + d] = lp1w[2 * 3 + d] * sc;
        s_lp1c[d] = (lp1b[d] - bnpm[d]) * sc + bnpb[d];
    }
    __syncthreads();

    // ---- pair setup ----
    const int k = tid & 15;
    const int nn = blockIdx.x * 12 + (tid >> 4);
    const bool valid = nn < n;
    const int nnc = valid ? nn : (n - 1);
    const int j = knn[(size_t)nnc * 16 + k];

    const float pr0 = p[(size_t)j * 3 + 0] - p[(size_t)nnc * 3 + 0];
    const float pr1 = p[(size_t)j * 3 + 1] - p[(size_t)nnc * 3 + 1];
    const float pr2 = p[(size_t)j * 3 + 2] - p[(size_t)nnc * 3 + 2];
    if (valid) {
        if (pr_out) {
            pr_out[((size_t)nn * 16 + k) * 3 + 0] = pr0;
            pr_out[((size_t)nn * 16 + k) * 3 + 1] = pr1;
            pr_out[((size_t)nn * 16 + k) * 3 + 2] = pr2;
        }
        if (knn_out) knn_out[(size_t)nn * 16 + k] = (float)j;
    }

    // ---- h = relu([pr, x_j] @ w01 + b01), all 16 in registers ----
    float h[16];
#pragma unroll
    for (int o4 = 0; o4 < 4; o4++) {
        float4 b = *(const float4*)(s_b01 + o4 * 4);
        h[o4 * 4 + 0] = b.x; h[o4 * 4 + 1] = b.y;
        h[o4 * 4 + 2] = b.z; h[o4 * 4 + 3] = b.w;
    }
#pragma unroll
    for (int r = 0; r < 3; r++) {
        const float pv = (r == 0) ? pr0 : ((r == 1) ? pr1 : pr2);
#pragma unroll
        for (int o4 = 0; o4 < 4; o4++) {
            float4 w = *(const float4*)(s_w01 + r * 16 + o4 * 4);
            h[o4 * 4 + 0] = fmaf(pv, w.x, h[o4 * 4 + 0]);
            h[o4 * 4 + 1] = fmaf(pv, w.y, h[o4 * 4 + 1]);
            h[o4 * 4 + 2] = fmaf(pv, w.z, h[o4 * 4 + 2]);
            h[o4 * 4 + 3] = fmaf(pv, w.w, h[o4 * 4 + 3]);
        }
    }
    {
        const float* xrow = x + (size_t)j * 64;
#pragma unroll 1
        for (int ch = 0; ch < 4; ch++) {           // 4 chunks of 16 inputs
            float4 xa = *(const float4*)(xrow + ch * 16 + 0);
            float4 xb = *(const float4*)(xrow + ch * 16 + 4);
            float4 xc = *(const float4*)(xrow + ch * 16 + 8);
            float4 xd = *(const float4*)(xrow + ch * 16 + 12);
            float in[16] = {xa.x, xa.y, xa.z, xa.w, xb.x, xb.y, xb.z, xb.w,
                            xc.x, xc.y, xc.z, xc.w, xd.x, xd.y, xd.z, xd.w};
            const float* wb = s_w01 + (3 + ch * 16) * 16;
#pragma unroll
            for (int e = 0; e < 16; e++) {
                const float iv = in[e];
#pragma unroll
                for (int o4 = 0; o4 < 4; o4++) {
                    float4 w = *(const float4*)(wb + e * 16 + o4 * 4);
                    h[o4 * 4 + 0] = fmaf(iv, w.x, h[o4 * 4 + 0]);
                    h[o4 * 4 + 1] = fmaf(iv, w.y, h[o4 * 4 + 1]);
                    h[o4 * 4 + 2] = fmaf(iv, w.z, h[o4 * 4 + 2]);
                    h[o4 * 4 + 3] = fmaf(iv, w.w, h[o4 * 4 + 3]);
                }
            }
        }
    }
    const int pb = tid * 17;
#pragma unroll
    for (int i = 0; i < 16; i++) {
        h[i] = fmaxf(h[i], 0.f);
        s_h[pb + i] = h[i];        // own-thread scratch for dynamic-i reads
    }

    // ---- energy[o] = blB[o] + sum_i h[i] * (sum_j blW[o,i,j] h[j]) ----
    float en[16];
#pragma unroll
    for (int o = 0; o < 16; o++) en[o] = s_blB[o];
#pragma unroll 1
    for (int i = 0; i < 16; i++) {
        const float hi = s_h[pb + i];
        const float* wbase = s_blW + i * 16;
#pragma unroll
        for (int o = 0; o < 16; o++) {
            const float4* wr = (const float4*)(wbase + o * 256);
            float4 w0 = wr[0], w1 = wr[1], w2 = wr[2], w3 = wr[3];
            float s = w0.x * h[0];
            s = fmaf(w0.y, h[1], s);  s = fmaf(w0.z, h[2], s);  s = fmaf(w0.w, h[3], s);
            s = fmaf(w1.x, h[4], s);  s = fmaf(w1.y, h[5], s);  s = fmaf(w1.z, h[6], s);
            s = fmaf(w1.w, h[7], s);  s = fmaf(w2.x, h[8], s);  s = fmaf(w2.y, h[9], s);
            s = fmaf(w2.z, h[10], s); s = fmaf(w2.w, h[11], s); s = fmaf(w3.x, h[12], s);
            s = fmaf(w3.y, h[13], s); s = fmaf(w3.z, h[14], s); s = fmaf(w3.w, h[15], s);
            en[o] = fmaf(hi, s, en[o]);
        }
    }

    // ---- q = relu(BN(pr @ lp1 + b)) ; shrink[u] = sum_a p_embed[a*16+u] ----
    const float q0 = fmaxf(fmaf(pr0, s_lp1f[0], fmaf(pr1, s_lp1f[4], fmaf(pr2, s_lp1f[8],  s_lp1c[0]))), 0.f);
    const float q1 = fmaxf(fmaf(pr0, s_lp1f[1], fmaf(pr1, s_lp1f[5], fmaf(pr2, s_lp1f[9],  s_lp1c[1]))), 0.f);
    const float q2 = fmaxf(fmaf(pr0, s_lp1f[2], fmaf(pr1, s_lp1f[6], fmaf(pr2, s_lp1f[10], s_lp1c[2]))), 0.f);

    float shr[16];
#pragma unroll
    for (int u = 0; u < 16; u++) shr[u] = 0.f;
#pragma unroll
    for (int c4 = 0; c4 < 16; c4++) {
        float4 l0 = *(const float4*)(s_lp2 + c4 * 4);
        float4 l1 = *(const float4*)(s_lp2 + 64 + c4 * 4);
        float4 l2 = *(const float4*)(s_lp2 + 128 + c4 * 4);
        float4 lb = *(const float4*)(s_lp2b + c4 * 4);
        const int u0 = (4 * c4) & 15;
        shr[u0 + 0] += fmaf(q0, l0.x, fmaf(q1, l1.x, fmaf(q2, l2.x, lb.x)));
        shr[u0 + 1] += fmaf(q0, l0.y, fmaf(q1, l1.y, fmaf(q2, l2.y, lb.y)));
        shr[u0 + 2] += fmaf(q0, l0.z, fmaf(q1, l1.z, fmaf(q2, l2.z, lb.z)));
        shr[u0 + 3] += fmaf(q0, l0.w, fmaf(q1, l1.w, fmaf(q2, l2.w, lb.w)));
    }

    // ---- h2a = relu(BN(e @ c2a)), e = [energy | shrink], fully unrolled ----
    float ev[32];
#pragma unroll
    for (int o = 0; o < 16; o++) ev[o] = en[o];
#pragma unroll
    for (int u = 0; u < 16; u++) ev[16 + u] = shr[u];

    float4 acc[16];
#pragma unroll
    for (int c4 = 0; c4 < 16; c4++) acc[c4] = make_float4(0.f, 0.f, 0.f, 0.f);
#pragma unroll
    for (int ei = 0; ei < 32; ei++) {
        const float v = ev[ei];
        const float4* wr = (const float4*)(s_c2a + ei * 64);
#pragma unroll
        for (int c4 = 0; c4 < 16; c4++) {
            float4 w = wr[c4];
            acc[c4].x = fmaf(v, w.x, acc[c4].x);
            acc[c4].y = fmaf(v, w.y, acc[c4].y);
            acc[c4].z = fmaf(v, w.z, acc[c4].z);
            acc[c4].w = fmaf(v, w.w, acc[c4].w);
        }
    }
#pragma unroll
    for (int c4 = 0; c4 < 16; c4++) {
        float4 sc = *(const float4*)(s_bn2as + c4 * 4);
        float4 sh = *(const float4*)(s_bn2at + c4 * 4);
        acc[c4].x = fmaxf(fmaf(acc[c4].x, sc.x, sh.x), 0.f);
        acc[c4].y = fmaxf(fmaf(acc[c4].y, sc.y, sh.y), 0.f);
        acc[c4].z = fmaxf(fmaf(acc[c4].z, sc.z, sh.z), 0.f);
        acc[c4].w = fmaxf(fmaf(acc[c4].w, sc.w, sh.w), 0.f);
    }

    // ---- h2b = relu(BN(h2a @ c2b)) ----
    float hb[8];
#pragma unroll
    for (int u = 0; u < 8; u++) hb[u] = 0.f;
#pragma unroll
    for (int c4 = 0; c4 < 16; c4++) {
        const float a0 = acc[c4].x, a1 = acc[c4].y, a2 = acc[c4].z, a3 = acc[c4].w;
        const float4* wr = (const float4*)(s_c2b + c4 * 32);
        float4 w0 = wr[0], w1 = wr[1], w2 = wr[2], w3 = wr[3];
        float4 w4 = wr[4], w5 = wr[5], w6 = wr[6], w7 = wr[7];
        hb[0] = fmaf(a0, w0.x, hb[0]); hb[1] = fmaf(a0, w0.y, hb[1]);
        hb[2] = fmaf(a0, w0.z, hb[2]); hb[3] = fmaf(a0, w0.w, hb[3]);
        hb[4] = fmaf(a0, w1.x, hb[4]); hb[5] = fmaf(a0, w1.y, hb[5]);
        hb[6] = fmaf(a0, w1.z, hb[6]); hb[7] = fmaf(a0, w1.w, hb[7]);
        hb[0] = fmaf(a1, w2.x, hb[0]); hb[1] = fmaf(a1, w2.y, hb[1]);
        hb[2] = fmaf(a1, w2.z, hb[2]); hb[3] = fmaf(a1, w2.w, hb[3]);
        hb[4] = fmaf(a1, w3.x, hb[4]); hb[5] = fmaf(a1, w3.y, hb[5]);
        hb[6] = fmaf(a1, w3.z, hb[6]); hb[7] = fmaf(a1, w3.w, hb[7]);
        hb[0] = fmaf(a2, w4.x, hb[0]); hb[1] = fmaf(a2, w4.y, hb[1]);
        hb[2] = fmaf(a2, w4.z, hb[2]); hb[3] = fmaf(a2, w4.w, hb[3]);
        hb[4] = fmaf(a2, w5.x, hb[4]); hb[5] = fmaf(a2, w5.y, hb[5]);
        hb[6] = fmaf(a2, w5.z, hb[6]); hb[7] = fmaf(a2, w5.w, hb[7]);
        hb[0] = fmaf(a3, w6.x, hb[0]); hb[1] = fmaf(a3, w6.y, hb[1]);
        hb[2] = fmaf(a3, w6.z, hb[2]); hb[3] = fmaf(a3, w6.w, hb[3]);
        hb[4] = fmaf(a3, w7.x, hb[4]); hb[5] = fmaf(a3, w7.y, hb[5]);
        hb[6] = fmaf(a3, w7.z, hb[6]); hb[7] = fmaf(a3, w7.w, hb[7]);
    }
#pragma unroll
    for (int u = 0; u < 8; u++)
        hb[u] = fmaxf(fmaf(hb[u], s_bn2bs[u], s_bn2bt[u]), 0.f);

    // ---- logits = h2b @ c2c + b ----
    float lg[8];
#pragma unroll
    for (int u = 0; u < 8; u++) lg[u] = s_c2cb[u];
#pragma unroll
    for (int u = 0; u < 8; u++) {
        const float4* wr = (const float4*)(s_c2c + u * 8);
        float4 w0 = wr[0], w1 = wr[1];
        lg[0] = fmaf(hb[u], w0.x, lg[0]); lg[1] = fmaf(hb[u], w0.y, lg[1]);
        lg[2] = fmaf(hb[u], w0.z, lg[2]); lg[3] = fmaf(hb[u], w0.w, lg[3]);
        lg[4] = fmaf(hb[u], w1.x, lg[4]); lg[5] = fmaf(hb[u], w1.y, lg[5]);
        lg[6] = fmaf(hb[u], w1.z, lg[6]); lg[7] = fmaf(hb[u], w1.w, lg[7]);
    }

    // ---- softmax over the 16 k-lanes (width-16 shuffle groups) ----
    float wsm[8];
#pragma unroll
    for (int c = 0; c < 8; c++) {
        float m = lg[c];
#pragma unroll
        for (int d = 8; d > 0; d >>= 1)
            m = fmaxf(m, __shfl_xor_sync(0xffffffffu, m, d));
        float ex = __expf(lg[c] - m);
        float sm = ex;
#pragma unroll
        for (int d = 8; d > 0; d >>= 1)
            sm += __shfl_xor_sync(0xffffffffu, sm, d);
        wsm[c] = ex / sm;
    }

    // ---- final: xk = (y[j] + p_embed) * w ; out = sum_k xk (shfl tree) ----
    const float* yrow = g_y + (size_t)j * 64;
    float* xkp = (valid && xk_out) ? (xk_out + ((size_t)nn * 16 + k) * 64) : nullptr;
#pragma unroll
    for (int c4 = 0; c4 < 16; c4++) {
        float4 l0 = *(const float4*)(s_lp2 + c4 * 4);
        float4 l1 = *(const float4*)(s_lp2 + 64 + c4 * 4);
        float4 l2 = *(const float4*)(s_lp2 + 128 + c4 * 4);
        float4 lb = *(const float4*)(s_lp2b + c4 * 4);
        float4 y4 = *(const float4*)(yrow + c4 * 4);
        const int w0i = (4 * c4) & 7;   // 0 or 4
        float4 v;
        v.x = (y4.x + fmaf(q0, l0.x, fmaf(q1, l1.x, fmaf(q2, l2.x, lb.x)))) * wsm[w0i + 0];
        v.y = (y4.y + fmaf(q0, l0.y, fmaf(q1, l1.y, fmaf(q2, l2.y, lb.y)))) * wsm[w0i + 1];
        v.z = (y4.z + fmaf(q0, l0.z, fmaf(q1, l1.z, fmaf(q2, l2.z, lb.z)))) * wsm[w0i + 2];
        v.w = (y4.w + fmaf(q0, l0.w, fmaf(q1, l1.w, fmaf(q2, l2.w, lb.w)))) * wsm[w0i + 3];
        if (xkp) *(float4*)(xkp + c4 * 4) = v;
#pragma unroll
        for (int d = 8; d > 0; d >>= 1) {
            v.x += __shfl_down_sync(0xffffffffu, v.x, d, 16);
            v.y += __shfl_down_sync(0xffffffffu, v.y, d, 16);
            v.z += __shfl_down_sync(0xffffffffu, v.z, d, 16);
            v.w += __shfl_down_sync(0xffffffffu, v.w, d, 16);
        }
        if (k == 0 && valid)
            *(float4*)(out + (size_t)nn * 64 + c4 * 4) = v;
    }
}

// ---------------------------------------------------------------------------
extern "C" void kernel_launch(void* const* d_in, const int* in_sizes, int n_in,
                              void* d_out, int out_size)
{
    const float* p    = (const float*)d_in[0];
    const float* x    = (const float*)d_in[1];
    const int*   knn  = (const int*)d_in[2];
    const float* w01  = (const float*)d_in[3];
    const float* b01  = (const float*)d_in[4];
    const float* blW  = (const float*)d_in[5];
    const float* blB  = (const float*)d_in[6];
    const float* lp1w = (const float*)d_in[7];
    const float* lp1b = (const float*)d_in[8];
    const float* bnpg = (const float*)d_in[9];
    const float* bnpb = (const float*)d_in[10];
    const float* bnpm = (const float*)d_in[11];
    const float* bnpv = (const float*)d_in[12];
    const float* lp2w = (const float*)d_in[13];
    const float* lp2b = (const float*)d_in[14];
    const float* c2aw = (const float*)d_in[15];
    const float* bn2ag = (const float*)d_in[16];
    const float* bn2ab = (const float*)d_in[17];
    const float* bn2am = (const float*)d_in[18];
    const float* bn2av = (const float*)d_in[19];
    const float* c2bw  = (const float*)d_in[20];
    const float* bn2bg = (const float*)d_in[21];
    const float* bn2bb = (const float*)d_in[22];
    const float* bn2bm = (const float*)d_in[23];
    const float* bn2bv = (const float*)d_in[24];
    const float* c2cw  = (const float*)d_in[25];
    const float* c2cb  = (const float*)d_in[26];
    const float* w03   = (const float*)d_in[27];
    const float* b03   = (const float*)d_in[28];

    const int n = in_sizes[0] / 3;
    float* out = (float*)d_out;

    const long long total = (long long)n * 64 + (long long)n * 16 * 64 +
                            (long long)n * 16 + (long long)n * 16 * 3;
    float* xk_out = nullptr;
    float* knn_out = nullptr;
    float* pr_out = nullptr;
    if ((long long)out_size >= total) {
        xk_out  = out + (size_t)n * 64;
        knn_out = xk_out + (size_t)n * 16 * 64;
        pr_out  = knn_out + (size_t)n * 16;
    }

    gemm_y_kernel<<<(n + 15) / 16, 256>>>(x, w03, b03, n);
    pm_main_kernel<<<(n + 11) / 12, 192>>>(p, x, knn, w01, b01, blW, blB,
                               lp1w, lp1b, bnpg, bnpb, bnpm, bnpv, lp2w, lp2b,
                               c2aw, bn2ag, bn2ab, bn2am, bn2av,
                               c2bw, bn2bg, bn2bb, bn2bm, bn2bv,
                               c2cw, c2cb,
                               out, xk_out, knn_out, pr_out, n);
}

// round 3
// speedup vs baseline: 3.0638x; 1.3322x over previous
#include <cuda_runtime.h>
#include <cstdint>

#define MAXN 100352

__device__ float g_y[MAXN * 64];   // x @ w03 + b03
__device__ float g_hx[MAXN * 16];  // x @ w01[3:] + b01

// ---------------------------------------------------------------------------
// Prep kernel: per point row, y[64] and hx[16]
// ---------------------------------------------------------------------------
__global__ void __launch_bounds__(256) prep_kernel(
    const float* __restrict__ x, const float* __restrict__ w03,
    const float* __restrict__ b03, const float* __restrict__ w01,
    const float* __restrict__ b01, int n)
{
    __shared__ float sw[64 * 64];
    __shared__ float sw1[64 * 16];   // w01 rows 3..66: [c][o]
    __shared__ float sx[16][64];
    const int tid = threadIdx.x;
    for (int i = tid; i < 4096; i += 256) sw[i] = w03[i];
    for (int i = tid; i < 1024; i += 256) sw1[i] = w01[48 + i];
    const int base = blockIdx.x * 16;
    const int c = tid & 63;
    const int rq = tid >> 6;
#pragma unroll
    for (int a = 0; a < 4; a++) {
        int r = rq * 4 + a;
        int row = base + r;
        sx[r][c] = (row < n) ? x[(size_t)row * 64 + c] : 0.f;
    }
    __syncthreads();
    const float bc = b03[c];
#pragma unroll
    for (int a = 0; a < 4; a++) {
        int r = rq + a * 4;
        int row = base + r;
        if (row < n) {
            float acc = bc;
#pragma unroll
            for (int d = 0; d < 64; d++) acc += sx[r][d] * sw[d * 64 + c];
            g_y[(size_t)row * 64 + c] = acc;
        }
    }
    // hx: one output per thread (16 rows x 16 outputs)
    {
        const int r = tid >> 4;
        const int o = tid & 15;
        const int row = base + r;
        if (row < n) {
            float acc = b01[o];
#pragma unroll
            for (int d = 0; d < 64; d++) acc += sx[r][d] * sw1[d * 16 + o];
            g_hx[(size_t)row * 16 + o] = acc;
        }
    }
}

// ---------------------------------------------------------------------------
// Main kernel: one thread handles P=2 (n,k) pairs. 256 threads = 32 points.
// ---------------------------------------------------------------------------
__global__ void __launch_bounds__(256, 2) pm_main_kernel(
    const float* __restrict__ p,
    const int* __restrict__ knn,
    const float* __restrict__ w01,
    const float* __restrict__ blW, const float* __restrict__ blB,
    const float* __restrict__ lp1w, const float* __restrict__ lp1b,
    const float* __restrict__ bnpg, const float* __restrict__ bnpb,
    const float* __restrict__ bnpm, const float* __restrict__ bnpv,
    const float* __restrict__ lp2w, const float* __restrict__ lp2b,
    const float* __restrict__ c2aw,
    const float* __restrict__ bn2ag, const float* __restrict__ bn2ab,
    const float* __restrict__ bn2am, const float* __restrict__ bn2av,
    const float* __restrict__ c2bw,
    const float* __restrict__ bn2bg, const float* __restrict__ bn2bb,
    const float* __restrict__ bn2bm, const float* __restrict__ bn2bv,
    const float* __restrict__ c2cw, const float* __restrict__ c2cb,
    float* __restrict__ out, float* __restrict__ xk_out,
    float* __restrict__ knn_out, float* __restrict__ pr_out,
    int n)
{
    __shared__ __align__(16) float s_blS[4096];   // [(i*16+jj)*16+o], symmetrized
    __shared__ __align__(16) float s_c2a[1024];   // top half [ei<16][c]
    __shared__ __align__(16) float s_c2aQ[192];   // [r][c]
    __shared__ __align__(16) float s_c2aC[64];    // const[c]
    __shared__ __align__(16) float s_c2b[512];    // [c][u]
    __shared__ __align__(16) float s_c2c[64];     // [u][o]
    __shared__ __align__(16) float s_lp2[192], s_lp2b[64];
    __shared__ __align__(16) float s_bn2as[64], s_bn2at[64];
    __shared__ __align__(16) float s_w01p[48];    // pr rows of w01 [r][o]
    __shared__ __align__(16) float s_blB[16];
    __shared__ __align__(16) float s_lp1f[12], s_lp1c[4];
    __shared__ __align__(16) float s_bn2bs[8], s_bn2bt[8], s_c2cb[8];
    __shared__ float s_M[48], s_s0[16];

    const int tid = threadIdx.x;

    // ---- staging phase A ----
    for (int id = tid; id < 4096; id += 256) {
        const int o = id & 15;
        const int pr = id >> 4;
        const int jj = pr & 15;
        const int i = pr >> 4;
        float v;
        if (i < jj)       v = blW[o * 256 + i * 16 + jj] + blW[o * 256 + jj * 16 + i];
        else if (i == jj) v = blW[o * 256 + i * 16 + i];
        else              v = 0.f;
        s_blS[id] = v;
    }
    for (int i = tid; i < 1024; i += 256) s_c2a[i] = c2aw[i];
    for (int i = tid; i < 512; i += 256) s_c2b[i] = c2bw[i];
    if (tid < 192) s_lp2[tid] = lp2w[tid];
    if (tid < 64) {
        s_lp2b[tid] = lp2b[tid];
        float sc = bn2ag[tid] * rsqrtf(bn2av[tid] + 1e-5f);
        s_bn2as[tid] = sc;
        s_bn2at[tid] = bn2ab[tid] - bn2am[tid] * sc;
        s_c2c[tid] = c2cw[tid];
    }
    if (tid < 48) {
        s_w01p[tid] = w01[tid];
        const int r = tid >> 4, u = tid & 15;
        s_M[tid] = lp2w[r * 64 + u] + lp2w[r * 64 + 16 + u] +
                   lp2w[r * 64 + 32 + u] + lp2w[r * 64 + 48 + u];
    }
    if (tid >= 48 && tid < 64) {
        const int u = tid - 48;
        s_s0[u] = lp2b[u] + lp2b[16 + u] + lp2b[32 + u] + lp2b[48 + u];
    }
    if (tid < 16) s_blB[tid] = blB[tid];
    if (tid < 8) {
        float sc = bn2bg[tid] * rsqrtf(bn2bv[tid] + 1e-5f);
        s_bn2bs[tid] = sc;
        s_bn2bt[tid] = bn2bb[tid] - bn2bm[tid] * sc;
        s_c2cb[tid] = c2cb[tid];
    }
    if (tid < 3) {
        const int d = tid;
        float sc = bnpg[d] * rsqrtf(bnpv[d] + 1e-5f);
        s_lp1f[0 + d] = lp1w[0 * 3 + d] * sc;
        s_lp1f[4 + d] = lp1w[1 * 3 + d] * sc;
        s_lp1f[8 + d] = lp1w[2 * 3 + d] * sc;
        s_lp1c[d] = (lp1b[d] - bnpm[d]) * sc + bnpb[d];
    }
    __syncthreads();
    // ---- staging phase B: c2aQ / c2aC from s_M / s_s0 ----
    if (tid < 192) {
        const int r = tid >> 6, c = tid & 63;
        float acc = 0.f;
#pragma unroll
        for (int u = 0; u < 16; u++)
            acc += s_M[r * 16 + u] * c2aw[(16 + u) * 64 + c];
        s_c2aQ[r * 64 + c] = acc;
    } else {
        const int c = tid - 192;
        float acc = 0.f;
#pragma unroll
        for (int u = 0; u < 16; u++)
            acc += s_s0[u] * c2aw[(16 + u) * 64 + c];
        s_c2aC[c] = acc;
    }
    __syncthreads();

    // ---- pair setup: warp covers 4 points, 2 via lane-half, 2 via P slot ----
    const int k = tid & 15;
    const int half = (tid >> 4) & 1;
    const int wrp = tid >> 5;
    const int base = blockIdx.x * 32 + wrp * 4 + half * 2;
    const int nn0 = base, nn1 = base + 1;
    const bool v0 = nn0 < n, v1 = nn1 < n;
    const int nc0 = v0 ? nn0 : (n > 0 ? n - 1 : 0);
    const int nc1 = v1 ? nn1 : (n > 0 ? n - 1 : 0);
    const int j0 = knn[(size_t)nc0 * 16 + k];
    const int j1 = knn[(size_t)nc1 * 16 + k];

    const float pA0 = p[(size_t)j0 * 3 + 0] - p[(size_t)nc0 * 3 + 0];
    const float pA1 = p[(size_t)j0 * 3 + 1] - p[(size_t)nc0 * 3 + 1];
    const float pA2 = p[(size_t)j0 * 3 + 2] - p[(size_t)nc0 * 3 + 2];
    const float pB0 = p[(size_t)j1 * 3 + 0] - p[(size_t)nc1 * 3 + 0];
    const float pB1 = p[(size_t)j1 * 3 + 1] - p[(size_t)nc1 * 3 + 1];
    const float pB2 = p[(size_t)j1 * 3 + 2] - p[(size_t)nc1 * 3 + 2];
    if (v0 && pr_out) {
        pr_out[((size_t)nn0 * 16 + k) * 3 + 0] = pA0;
        pr_out[((size_t)nn0 * 16 + k) * 3 + 1] = pA1;
        pr_out[((size_t)nn0 * 16 + k) * 3 + 2] = pA2;
    }
    if (v1 && pr_out) {
        pr_out[((size_t)nn1 * 16 + k) * 3 + 0] = pB0;
        pr_out[((size_t)nn1 * 16 + k) * 3 + 1] = pB1;
        pr_out[((size_t)nn1 * 16 + k) * 3 + 2] = pB2;
    }
    if (v0 && knn_out) knn_out[(size_t)nn0 * 16 + k] = (float)j0;
    if (v1 && knn_out) knn_out[(size_t)nn1 * 16 + k] = (float)j1;

    // ---- h = relu(hx[j] + pr @ w01p) ----
    float h0[16], h1[16];
    {
        const float4* hxa = (const float4*)(g_hx + (size_t)j0 * 16);
        const float4* hxb = (const float4*)(g_hx + (size_t)j1 * 16);
#pragma unroll
        for (int o4 = 0; o4 < 4; o4++) {
            float4 a = hxa[o4], b = hxb[o4];
            float4 w0 = *(const float4*)(s_w01p + o4 * 4);
            float4 w1 = *(const float4*)(s_w01p + 16 + o4 * 4);
            float4 w2 = *(const float4*)(s_w01p + 32 + o4 * 4);
            h0[o4 * 4 + 0] = fmaxf(a.x + pA0 * w0.x + pA1 * w1.x + pA2 * w2.x, 0.f);
            h0[o4 * 4 + 1] = fmaxf(a.y + pA0 * w0.y + pA1 * w1.y + pA2 * w2.y, 0.f);
            h0[o4 * 4 + 2] = fmaxf(a.z + pA0 * w0.z + pA1 * w1.z + pA2 * w2.z, 0.f);
            h0[o4 * 4 + 3] = fmaxf(a.w + pA0 * w0.w + pA1 * w1.w + pA2 * w2.w, 0.f);
            h1[o4 * 4 + 0] = fmaxf(b.x + pB0 * w0.x + pB1 * w1.x + pB2 * w2.x, 0.f);
            h1[o4 * 4 + 1] = fmaxf(b.y + pB0 * w0.y + pB1 * w1.y + pB2 * w2.y, 0.f);
            h1[o4 * 4 + 2] = fmaxf(b.z + pB0 * w0.z + pB1 * w1.z + pB2 * w2.z, 0.f);
            h1[o4 * 4 + 3] = fmaxf(b.w + pB0 * w0.w + pB1 * w1.w + pB2 * w2.w, 0.f);
        }
    }

    // ---- energy via symmetrized bilinear ----
    float e0[16], e1[16];
#pragma unroll
    for (int o4 = 0; o4 < 4; o4++) {
        float4 b = *(const float4*)(s_blB + o4 * 4);
        e0[o4 * 4 + 0] = b.x; e0[o4 * 4 + 1] = b.y; e0[o4 * 4 + 2] = b.z; e0[o4 * 4 + 3] = b.w;
        e1[o4 * 4 + 0] = b.x; e1[o4 * 4 + 1] = b.y; e1[o4 * 4 + 2] = b.z; e1[o4 * 4 + 3] = b.w;
    }
#pragma unroll
    for (int i = 0; i < 16; i++) {
#pragma unroll
        for (int jj = i; jj < 16; jj++) {
            const float ga = h0[i] * h0[jj];
            const float gb = h1[i] * h1[jj];
            const float4* wr = (const float4*)(s_blS + (i * 16 + jj) * 16);
            float4 w0 = wr[0], w1 = wr[1], w2 = wr[2], w3 = wr[3];
            e0[0] = fmaf(ga, w0.x, e0[0]);  e1[0] = fmaf(gb, w0.x, e1[0]);
            e0[1] = fmaf(ga, w0.y, e0[1]);  e1[1] = fmaf(gb, w0.y, e1[1]);
            e0[2] = fmaf(ga, w0.z, e0[2]);  e1[2] = fmaf(gb, w0.z, e1[2]);
            e0[3] = fmaf(ga, w0.w, e0[3]);  e1[3] = fmaf(gb, w0.w, e1[3]);
            e0[4] = fmaf(ga, w1.x, e0[4]);  e1[4] = fmaf(gb, w1.x, e1[4]);
            e0[5] = fmaf(ga, w1.y, e0[5]);  e1[5] = fmaf(gb, w1.y, e1[5]);
            e0[6] = fmaf(ga, w1.z, e0[6]);  e1[6] = fmaf(gb, w1.z, e1[6]);
            e0[7] = fmaf(ga, w1.w, e0[7]);  e1[7] = fmaf(gb, w1.w, e1[7]);
            e0[8] = fmaf(ga, w2.x, e0[8]);  e1[8] = fmaf(gb, w2.x, e1[8]);
            e0[9] = fmaf(ga, w2.y, e0[9]);  e1[9] = fmaf(gb, w2.y, e1[9]);
            e0[10] = fmaf(ga, w2.z, e0[10]); e1[10] = fmaf(gb, w2.z, e1[10]);
            e0[11] = fmaf(ga, w2.w, e0[11]); e1[11] = fmaf(gb, w2.w, e1[11]);
            e0[12] = fmaf(ga, w3.x, e0[12]); e1[12] = fmaf(gb, w3.x, e1[12]);
            e0[13] = fmaf(ga, w3.y, e0[13]); e1[13] = fmaf(gb, w3.y, e1[13]);
            e0[14] = fmaf(ga, w3.z, e0[14]); e1[14] = fmaf(gb, w3.z, e1[14]);
            e0[15] = fmaf(ga, w3.w, e0[15]); e1[15] = fmaf(gb, w3.w, e1[15]);
        }
    }

    // ---- q = relu(BN(pr @ lp1)) per slot ----
    float qa[3], qb[3];
#pragma unroll
    for (int d = 0; d < 3; d++) {
        qa[d] = fmaxf(fmaf(pA0, s_lp1f[d], fmaf(pA1, s_lp1f[4 + d], fmaf(pA2, s_lp1f[8 + d], s_lp1c[d]))), 0.f);
        qb[d] = fmaxf(fmaf(pB0, s_lp1f[d], fmaf(pB1, s_lp1f[4 + d], fmaf(pB2, s_lp1f[8 + d], s_lp1c[d]))), 0.f);
    }

    // ---- fused c2a(+q-fold)+BN+relu+c2b, channel blocks of 16 ----
    float hb0[8], hb1[8];
#pragma unroll
    for (int u = 0; u < 8; u++) { hb0[u] = 0.f; hb1[u] = 0.f; }
#pragma unroll
    for (int cb = 0; cb < 4; cb++) {
        float a0[16], a1[16];
#pragma unroll
        for (int c4 = 0; c4 < 4; c4++) {
            float4 cc = *(const float4*)(s_c2aC + cb * 16 + c4 * 4);
            a0[c4 * 4 + 0] = cc.x; a0[c4 * 4 + 1] = cc.y; a0[c4 * 4 + 2] = cc.z; a0[c4 * 4 + 3] = cc.w;
            a1[c4 * 4 + 0] = cc.x; a1[c4 * 4 + 1] = cc.y; a1[c4 * 4 + 2] = cc.z; a1[c4 * 4 + 3] = cc.w;
        }
#pragma unroll
        for (int ei = 0; ei < 16; ei++) {
            const float va = e0[ei], vb = e1[ei];
            const float4* wr = (const float4*)(s_c2a + ei * 64 + cb * 16);
#pragma unroll
            for (int c4 = 0; c4 < 4; c4++) {
                float4 w = wr[c4];
                a0[c4 * 4 + 0] = fmaf(va, w.x, a0[c4 * 4 + 0]); a1[c4 * 4 + 0] = fmaf(vb, w.x, a1[c4 * 4 + 0]);
                a0[c4 * 4 + 1] = fmaf(va, w.y, a0[c4 * 4 + 1]); a1[c4 * 4 + 1] = fmaf(vb, w.y, a1[c4 * 4 + 1]);
                a0[c4 * 4 + 2] = fmaf(va, w.z, a0[c4 * 4 + 2]); a1[c4 * 4 + 2] = fmaf(vb, w.z, a1[c4 * 4 + 2]);
                a0[c4 * 4 + 3] = fmaf(va, w.w, a0[c4 * 4 + 3]); a1[c4 * 4 + 3] = fmaf(vb, w.w, a1[c4 * 4 + 3]);
            }
        }
#pragma unroll
        for (int r = 0; r < 3; r++) {
            const float va = qa[r], vb = qb[r];
            const float4* wr = (const float4*)(s_c2aQ + r * 64 + cb * 16);
#pragma unroll
            for (int c4 = 0; c4 < 4; c4++) {
                float4 w = wr[c4];
                a0[c4 * 4 + 0] = fmaf(va, w.x, a0[c4 * 4 + 0]); a1[c4 * 4 + 0] = fmaf(vb, w.x, a1[c4 * 4 + 0]);
                a0[c4 * 4 + 1] = fmaf(va, w.y, a0[c4 * 4 + 1]); a1[c4 * 4 + 1] = fmaf(vb, w.y, a1[c4 * 4 + 1]);
                a0[c4 * 4 + 2] = fmaf(va, w.z, a0[c4 * 4 + 2]); a1[c4 * 4 + 2] = fmaf(vb, w.z, a1[c4 * 4 + 2]);
                a0[c4 * 4 + 3] = fmaf(va, w.w, a0[c4 * 4 + 3]); a1[c4 * 4 + 3] = fmaf(vb, w.w, a1[c4 * 4 + 3]);
            }
        }
        // BN + relu
#pragma unroll
        for (int c4 = 0; c4 < 4; c4++) {
            float4 sc = *(const float4*)(s_bn2as + cb * 16 + c4 * 4);
            float4 sh = *(const float4*)(s_bn2at + cb * 16 + c4 * 4);
            a0[c4 * 4 + 0] = fmaxf(fmaf(a0[c4 * 4 + 0], sc.x, sh.x), 0.f);
            a0[c4 * 4 + 1] = fmaxf(fmaf(a0[c4 * 4 + 1], sc.y, sh.y), 0.f);
            a0[c4 * 4 + 2] = fmaxf(fmaf(a0[c4 * 4 + 2], sc.z, sh.z), 0.f);
            a0[c4 * 4 + 3] = fmaxf(fmaf(a0[c4 * 4 + 3], sc.w, sh.w), 0.f);
            a1[c4 * 4 + 0] = fmaxf(fmaf(a1[c4 * 4 + 0], sc.x, sh.x), 0.f);
            a1[c4 * 4 + 1] = fmaxf(fmaf(a1[c4 * 4 + 1], sc.y, sh.y), 0.f);
            a1[c4 * 4 + 2] = fmaxf(fmaf(a1[c4 * 4 + 2], sc.z, sh.z), 0.f);
            a1[c4 * 4 + 3] = fmaxf(fmaf(a1[c4 * 4 + 3], sc.w, sh.w), 0.f);
        }
        // c2b accumulation
#pragma unroll
        for (int c = 0; c < 16; c++) {
            const int cc = cb * 16 + c;
            const float4* wr = (const float4*)(s_c2b + cc * 8);
            float4 w0 = wr[0], w1 = wr[1];
            const float va = a0[c], vb = a1[c];
            hb0[0] = fmaf(va, w0.x, hb0[0]); hb1[0] = fmaf(vb, w0.x, hb1[0]);
            hb0[1] = fmaf(va, w0.y, hb0[1]); hb1[1] = fmaf(vb, w0.y, hb1[1]);
            hb0[2] = fmaf(va, w0.z, hb0[2]); hb1[2] = fmaf(vb, w0.z, hb1[2]);
            hb0[3] = fmaf(va, w0.w, hb0[3]); hb1[3] = fmaf(vb, w0.w, hb1[3]);
            hb0[4] = fmaf(va, w1.x, hb0[4]); hb1[4] = fmaf(vb, w1.x, hb1[4]);
            hb0[5] = fmaf(va, w1.y, hb0[5]); hb1[5] = fmaf(vb, w1.y, hb1[5]);
            hb0[6] = fmaf(va, w1.z, hb0[6]); hb1[6] = fmaf(vb, w1.z, hb1[6]);
            hb0[7] = fmaf(va, w1.w, hb0[7]); hb1[7] = fmaf(vb, w1.w, hb1[7]);
        }
    }
#pragma unroll
    for (int u = 0; u < 8; u++) {
        hb0[u] = fmaxf(fmaf(hb0[u], s_bn2bs[u], s_bn2bt[u]), 0.f);
        hb1[u] = fmaxf(fmaf(hb1[u], s_bn2bs[u], s_bn2bt[u]), 0.f);
    }

    // ---- logits ----
    float lg0[8], lg1[8];
#pragma unroll
    for (int u = 0; u < 8; u++) { lg0[u] = s_c2cb[u]; lg1[u] = s_c2cb[u]; }
#pragma unroll
    for (int u = 0; u < 8; u++) {
        const float4* wr = (const float4*)(s_c2c + u * 8);
        float4 w0 = wr[0], w1 = wr[1];
        lg0[0] = fmaf(hb0[u], w0.x, lg0[0]); lg1[0] = fmaf(hb1[u], w0.x, lg1[0]);
        lg0[1] = fmaf(hb0[u], w0.y, lg0[1]); lg1[1] = fmaf(hb1[u], w0.y, lg1[1]);
        lg0[2] = fmaf(hb0[u], w0.z, lg0[2]); lg1[2] = fmaf(hb1[u], w0.z, lg1[2]);
        lg0[3] = fmaf(hb0[u], w0.w, lg0[3]); lg1[3] = fmaf(hb1[u], w0.w, lg1[3]);
        lg0[4] = fmaf(hb0[u], w1.x, lg0[4]); lg1[4] = fmaf(hb1[u], w1.x, lg1[4]);
        lg0[5] = fmaf(hb0[u], w1.y, lg0[5]); lg1[5] = fmaf(hb1[u], w1.y, lg1[5]);
        lg0[6] = fmaf(hb0[u], w1.z, lg0[6]); lg1[6] = fmaf(hb1[u], w1.z, lg1[6]);
        lg0[7] = fmaf(hb0[u], w1.w, lg0[7]); lg1[7] = fmaf(hb1[u], w1.w, lg1[7]);
    }

    // ---- softmax over 16 k-lanes (width-16 groups), per slot ----
    float ws0[8], ws1[8];
#pragma unroll
    for (int c = 0; c < 8; c++) {
        float m0 = lg0[c], m1 = lg1[c];
#pragma unroll
        for (int d = 8; d > 0; d >>= 1) {
            m0 = fmaxf(m0, __shfl_xor_sync(0xffffffffu, m0, d));
            m1 = fmaxf(m1, __shfl_xor_sync(0xffffffffu, m1, d));
        }
        float x0 = __expf(lg0[c] - m0);
        float x1 = __expf(lg1[c] - m1);
        float s0 = x0, s1 = x1;
#pragma unroll
        for (int d = 8; d > 0; d >>= 1) {
            s0 += __shfl_xor_sync(0xffffffffu, s0, d);
            s1 += __shfl_xor_sync(0xffffffffu, s1, d);
        }
        ws0[c] = x0 / s0;
        ws1[c] = x1 / s1;
    }

    // ---- epilogue per slot: xk = (y[j] + p_embed) * w ; out = sum_k ----
    {
        const float* yr0 = g_y + (size_t)j0 * 64;
        const float* yr1 = g_y + (size_t)j1 * 64;
        float* xp0 = (v0 && xk_out) ? (xk_out + ((size_t)nn0 * 16 + k) * 64) : nullptr;
        float* xp1 = (v1 && xk_out) ? (xk_out + ((size_t)nn1 * 16 + k) * 64) : nullptr;
#pragma unroll
        for (int c4 = 0; c4 < 16; c4++) {
            float4 l0 = *(const float4*)(s_lp2 + c4 * 4);
            float4 l1 = *(const float4*)(s_lp2 + 64 + c4 * 4);
            float4 l2 = *(const float4*)(s_lp2 + 128 + c4 * 4);
            float4 lb = *(const float4*)(s_lp2b + c4 * 4);
            float4 y0 = *(const float4*)(yr0 + c4 * 4);
            float4 y1 = *(const float4*)(yr1 + c4 * 4);
            const int w0i = (4 * c4) & 7;
            float4 vv0, vv1;
            vv0.x = (y0.x + fmaf(qa[0], l0.x, fmaf(qa[1], l1.x, fmaf(qa[2], l2.x, lb.x)))) * ws0[w0i + 0];
            vv0.y = (y0.y + fmaf(qa[0], l0.y, fmaf(qa[1], l1.y, fmaf(qa[2], l2.y, lb.y)))) * ws0[w0i + 1];
            vv0.z = (y0.z + fmaf(qa[0], l0.z, fmaf(qa[1], l1.z, fmaf(qa[2], l2.z, lb.z)))) * ws0[w0i + 2];
            vv0.w = (y0.w + fmaf(qa[0], l0.w, fmaf(qa[1], l1.w, fmaf(qa[2], l2.w, lb.w)))) * ws0[w0i + 3];
            vv1.x = (y1.x + fmaf(qb[0], l0.x, fmaf(qb[1], l1.x, fmaf(qb[2], l2.x, lb.x)))) * ws1[w0i + 0];
            vv1.y = (y1.y + fmaf(qb[0], l0.y, fmaf(qb[1], l1.y, fmaf(qb[2], l2.y, lb.y)))) * ws1[w0i + 1];
            vv1.z = (y1.z + fmaf(qb[0], l0.z, fmaf(qb[1], l1.z, fmaf(qb[2], l2.z, lb.z)))) * ws1[w0i + 2];
            vv1.w = (y1.w + fmaf(qb[0], l0.w, fmaf(qb[1], l1.w, fmaf(qb[2], l2.w, lb.w)))) * ws1[w0i + 3];
            if (xp0) *(float4*)(xp0 + c4 * 4) = vv0;
            if (xp1) *(float4*)(xp1 + c4 * 4) = vv1;
#pragma unroll
            for (int d = 8; d > 0; d >>= 1) {
                vv0.x += __shfl_down_sync(0xffffffffu, vv0.x, d, 16);
                vv0.y += __shfl_down_sync(0xffffffffu, vv0.y, d, 16);
                vv0.z += __shfl_down_sync(0xffffffffu, vv0.z, d, 16);
                vv0.w += __shfl_down_sync(0xffffffffu, vv0.w, d, 16);
                vv1.x += __shfl_down_sync(0xffffffffu, vv1.x, d, 16);
                vv1.y += __shfl_down_sync(0xffffffffu, vv1.y, d, 16);
                vv1.z += __shfl_down_sync(0xffffffffu, vv1.z, d, 16);
                vv1.w += __shfl_down_sync(0xffffffffu, vv1.w, d, 16);
            }
            if (k == 0) {
                if (v0) *(float4*)(out + (size_t)nn0 * 64 + c4 * 4) = vv0;
                if (v1) *(float4*)(out + (size_t)nn1 * 64 + c4 * 4) = vv1;
            }
        }
    }
}

// ---------------------------------------------------------------------------
extern "C" void kernel_launch(void* const* d_in, const int* in_sizes, int n_in,
                              void* d_out, int out_size)
{
    const float* p    = (const float*)d_in[0];
    const float* x    = (const float*)d_in[1];
    const int*   knn  = (const int*)d_in[2];
    const float* w01  = (const float*)d_in[3];
    const float* b01  = (const float*)d_in[4];
    const float* blW  = (const float*)d_in[5];
    const float* blB  = (const float*)d_in[6];
    const float* lp1w = (const float*)d_in[7];
    const float* lp1b = (const float*)d_in[8];
    const float* bnpg = (const float*)d_in[9];
    const float* bnpb = (const float*)d_in[10];
    const float* bnpm = (const float*)d_in[11];
    const float* bnpv = (const float*)d_in[12];
    const float* lp2w = (const float*)d_in[13];
    const float* lp2b = (const float*)d_in[14];
    const float* c2aw = (const float*)d_in[15];
    const float* bn2ag = (const float*)d_in[16];
    const float* bn2ab = (const float*)d_in[17];
    const float* bn2am = (const float*)d_in[18];
    const float* bn2av = (const float*)d_in[19];
    const float* c2bw  = (const float*)d_in[20];
    const float* bn2bg = (const float*)d_in[21];
    const float* bn2bb = (const float*)d_in[22];
    const float* bn2bm = (const float*)d_in[23];
    const float* bn2bv = (const float*)d_in[24];
    const float* c2cw  = (const float*)d_in[25];
    const float* c2cb  = (const float*)d_in[26];
    const float* w03   = (const float*)d_in[27];
    const float* b03   = (const float*)d_in[28];

    const int n = in_sizes[0] / 3;
    float* out = (float*)d_out;

    const long long total = (long long)n * 64 + (long long)n * 16 * 64 +
                            (long long)n * 16 + (long long)n * 16 * 3;
    float* xk_out = nullptr;
    float* knn_out = nullptr;
    float* pr_out = nullptr;
    if ((long long)out_size >= total) {
        xk_out  = out + (size_t)n * 64;
        knn_out = xk_out + (size_t)n * 16 * 64;
        pr_out  = knn_out + (size_t)n * 16;
    }

    prep_kernel<<<(n + 15) / 16, 256>>>(x, w03, b03, w01, b01, n);
    pm_main_kernel<<<(n + 31) / 32, 256>>>(p, knn, w01, blW, blB,
                               lp1w, lp1b, bnpg, bnpb, bnpm, bnpv, lp2w, lp2b,
                               c2aw, bn2ag, bn2ab, bn2am, bn2av,
                               c2bw, bn2bg, bn2bb, bn2bm, bn2bv,
                               c2cw, c2cb,
                               out, xk_out, knn_out, pr_out, n);
}

// round 4
// speedup vs baseline: 5.4822x; 1.7893x over previous
#include <cuda_runtime.h>
#include <cstdint>

#define MAXN 100352

typedef unsigned long long ull;

__device__ float g_y[MAXN * 64];   // x @ w03 + b03
__device__ float g_hx[MAXN * 16];  // x @ w01[3:] + b01
__device__ float g_blS[4096];      // symmetrized bilinear [(i*16+jj)*16+o]
__device__ float g_c2aQ[192];      // folded q->c2a
__device__ float g_c2aC[64];       // folded const->c2a

// ---- packed f32x2 helpers (FFMA2) ----
__device__ __forceinline__ ull pk2(float lo, float hi) {
    ull r; asm("mov.b64 %0,{%1,%2};" : "=l"(r) : "f"(lo), "f"(hi)); return r;
}
__device__ __forceinline__ ull bc2(float v) { return pk2(v, v); }
__device__ __forceinline__ void upk2(ull v, float& lo, float& hi) {
    asm("mov.b64 {%0,%1},%2;" : "=f"(lo), "=f"(hi) : "l"(v));
}
__device__ __forceinline__ ull fma2_(ull a, ull b, ull c) {
    ull d; asm("fma.rn.f32x2 %0,%1,%2,%3;" : "=l"(d) : "l"(a), "l"(b), "l"(c)); return d;
}
__device__ __forceinline__ ull add2_(ull a, ull b) {
    ull d; asm("add.rn.f32x2 %0,%1,%2;" : "=l"(d) : "l"(a), "l"(b)); return d;
}
__device__ __forceinline__ ull mul2_(ull a, ull b) {
    ull d; asm("mul.rn.f32x2 %0,%1,%2;" : "=l"(d) : "l"(a), "l"(b)); return d;
}

// ---------------------------------------------------------------------------
// Setup kernel (17 blocks): symmetrize blW; fold shrink into c2a.
// ---------------------------------------------------------------------------
__global__ void __launch_bounds__(256) setup_kernel(
    const float* __restrict__ blW, const float* __restrict__ c2aw,
    const float* __restrict__ lp2w, const float* __restrict__ lp2b)
{
    const int tid = threadIdx.x;
    if (blockIdx.x < 16) {
        const int id = blockIdx.x * 256 + tid;
        const int o = id & 15;
        const int pr = id >> 4;
        const int jj = pr & 15;
        const int i = pr >> 4;
        float v;
        if (i < jj)       v = blW[o * 256 + i * 16 + jj] + blW[o * 256 + jj * 16 + i];
        else if (i == jj) v = blW[o * 256 + i * 16 + i];
        else              v = 0.f;
        g_blS[id] = v;
    } else {
        __shared__ float sM[48], s0[16];
        if (tid < 48) {
            const int r = tid >> 4, u = tid & 15;
            sM[tid] = lp2w[r * 64 + u] + lp2w[r * 64 + 16 + u] +
                      lp2w[r * 64 + 32 + u] + lp2w[r * 64 + 48 + u];
        }
        if (tid >= 48 && tid < 64) {
            const int u = tid - 48;
            s0[u] = lp2b[u] + lp2b[16 + u] + lp2b[32 + u] + lp2b[48 + u];
        }
        __syncthreads();
        if (tid < 192) {
            const int r = tid >> 6, c = tid & 63;
            float acc = 0.f;
#pragma unroll
            for (int u = 0; u < 16; u++)
                acc += sM[r * 16 + u] * c2aw[(16 + u) * 64 + c];
            g_c2aQ[r * 64 + c] = acc;
        } else {
            const int c = tid - 192;
            float acc = 0.f;
#pragma unroll
            for (int u = 0; u < 16; u++)
                acc += s0[u] * c2aw[(16 + u) * 64 + c];
            g_c2aC[c] = acc;
        }
    }
}

// ---------------------------------------------------------------------------
// Prep kernel: 32 rows/block. y via packed channel pairs; hx per-thread.
// ---------------------------------------------------------------------------
__global__ void __launch_bounds__(256) prep_kernel(
    const float* __restrict__ x, const float* __restrict__ w03,
    const float* __restrict__ b03, const float* __restrict__ w01,
    const float* __restrict__ b01, int n)
{
    __shared__ float sw[4096];
    __shared__ float sw1[1024];
    __shared__ float sx[32][64];
    const int tid = threadIdx.x;
    for (int i = tid; i < 1024; i += 256)
        ((float4*)sw)[i] = ((const float4*)w03)[i];
    for (int i = tid; i < 256; i += 256)
        ((float4*)sw1)[i] = ((const float4*)(w01 + 48))[i];
    const int base = blockIdx.x * 32;
    {
        const int c4 = tid & 15;
        const int r = tid >> 4;
#pragma unroll
        for (int a = 0; a < 2; a++) {
            const int row = base + r + a * 16;
            float4 v = make_float4(0.f, 0.f, 0.f, 0.f);
            if (row < n) v = ((const float4*)(x + (size_t)row * 64))[c4];
            ((float4*)sx[r + a * 16])[c4] = v;
        }
    }
    __syncthreads();

    // y: thread = (rq=tid>>5 in 0..7, cp=tid&31 -> channels 2cp,2cp+1), 4 rows
    {
        const int rq = tid >> 5;
        const int cp = tid & 31;
        const ull bcp = ((const ull*)b03)[cp];
        ull acc0 = bcp, acc1 = bcp, acc2 = bcp, acc3 = bcp;
#pragma unroll 8
        for (int d = 0; d < 64; d++) {
            const ull w2 = ((const ull*)(sw + d * 64))[cp];
            acc0 = fma2_(bc2(sx[rq * 4 + 0][d]), w2, acc0);
            acc1 = fma2_(bc2(sx[rq * 4 + 1][d]), w2, acc1);
            acc2 = fma2_(bc2(sx[rq * 4 + 2][d]), w2, acc2);
            acc3 = fma2_(bc2(sx[rq * 4 + 3][d]), w2, acc3);
        }
        const int r0 = base + rq * 4;
        if (r0 + 0 < n) ((ull*)(g_y + (size_t)(r0 + 0) * 64))[cp] = acc0;
        if (r0 + 1 < n) ((ull*)(g_y + (size_t)(r0 + 1) * 64))[cp] = acc1;
        if (r0 + 2 < n) ((ull*)(g_y + (size_t)(r0 + 2) * 64))[cp] = acc2;
        if (r0 + 3 < n) ((ull*)(g_y + (size_t)(r0 + 3) * 64))[cp] = acc3;
    }
    // hx: thread = (r=tid>>3 in 0..31, o8=tid&7 -> channels 2o8,2o8+1)
    {
        const int r = tid >> 3;
        const int o8 = tid & 7;
        ull acc = ((const ull*)b01)[o8];
#pragma unroll 8
        for (int d = 0; d < 64; d++)
            acc = fma2_(bc2(sx[r][d]), ((const ull*)(sw1 + d * 16))[o8], acc);
        const int row = base + r;
        if (row < n) ((ull*)(g_hx + (size_t)row * 16))[o8] = acc;
    }
}

// ---------------------------------------------------------------------------
// Main kernel: one thread = 2 (n,k) pairs, packed-f32x2 math throughout.
// ---------------------------------------------------------------------------
__global__ void __launch_bounds__(256, 2) pm_main_kernel(
    const float* __restrict__ p,
    const int* __restrict__ knn,
    const float* __restrict__ w01, const float* __restrict__ blB,
    const float* __restrict__ lp1w, const float* __restrict__ lp1b,
    const float* __restrict__ bnpg, const float* __restrict__ bnpb,
    const float* __restrict__ bnpm, const float* __restrict__ bnpv,
    const float* __restrict__ lp2w, const float* __restrict__ lp2b,
    const float* __restrict__ c2aw,
    const float* __restrict__ bn2ag, const float* __restrict__ bn2ab,
    const float* __restrict__ bn2am, const float* __restrict__ bn2av,
    const float* __restrict__ c2bw,
    const float* __restrict__ bn2bg, const float* __restrict__ bn2bb,
    const float* __restrict__ bn2bm, const float* __restrict__ bn2bv,
    const float* __restrict__ c2cw, const float* __restrict__ c2cb,
    float* __restrict__ out, float* __restrict__ xk_out,
    float* __restrict__ knn_out, float* __restrict__ pr_out,
    int n)
{
    __shared__ __align__(16) float s_blS[4096];
    __shared__ __align__(16) float s_c2a[1024];
    __shared__ __align__(16) float s_c2aQ[192];
    __shared__ __align__(16) float s_c2aC[64];
    __shared__ __align__(16) float s_c2b[512];
    __shared__ __align__(16) float s_c2c[64];
    __shared__ __align__(16) float s_lp2[192], s_lp2b[64];
    __shared__ __align__(16) float s_bn2as[64], s_bn2at[64];
    __shared__ __align__(16) float s_w01p[48];
    __shared__ __align__(16) float s_blB[16];
    __shared__ __align__(16) float s_lp1f[12], s_lp1c[4];
    __shared__ __align__(16) float s_bn2bs[8], s_bn2bt[8], s_c2cb[8];

    const int tid = threadIdx.x;

    // ---- staging (all linear) ----
#pragma unroll
    for (int i = 0; i < 4; i++)
        ((float4*)s_blS)[tid + i * 256] = ((const float4*)g_blS)[tid + i * 256];
    ((float4*)s_c2a)[tid] = ((const float4*)c2aw)[tid];
    if (tid < 128) ((float4*)s_c2b)[tid] = ((const float4*)c2bw)[tid];
    if (tid < 192) { s_c2aQ[tid] = g_c2aQ[tid]; s_lp2[tid] = lp2w[tid]; }
    if (tid < 64) {
        s_c2aC[tid] = g_c2aC[tid];
        s_lp2b[tid] = lp2b[tid];
        float sc = bn2ag[tid] * rsqrtf(bn2av[tid] + 1e-5f);
        s_bn2as[tid] = sc;
        s_bn2at[tid] = bn2ab[tid] - bn2am[tid] * sc;
        s_c2c[tid] = c2cw[tid];
    }
    if (tid < 48) s_w01p[tid] = w01[tid];
    if (tid < 16) s_blB[tid] = blB[tid];
    if (tid < 8) {
        float sc = bn2bg[tid] * rsqrtf(bn2bv[tid] + 1e-5f);
        s_bn2bs[tid] = sc;
        s_bn2bt[tid] = bn2bb[tid] - bn2bm[tid] * sc;
        s_c2cb[tid] = c2cb[tid];
    }
    if (tid < 3) {
        const int d = tid;
        float sc = bnpg[d] * rsqrtf(bnpv[d] + 1e-5f);
        s_lp1f[0 + d] = lp1w[0 * 3 + d] * sc;
        s_lp1f[4 + d] = lp1w[1 * 3 + d] * sc;
        s_lp1f[8 + d] = lp1w[2 * 3 + d] * sc;
        s_lp1c[d] = (lp1b[d] - bnpm[d]) * sc + bnpb[d];
    }
    __syncthreads();

    // ---- pair setup ----
    const int k = tid & 15;
    const int half = (tid >> 4) & 1;
    const int wrp = tid >> 5;
    const int base = blockIdx.x * 32 + wrp * 4 + half * 2;
    const int nn0 = base, nn1 = base + 1;
    const bool v0 = nn0 < n, v1 = nn1 < n;
    const int nc0 = v0 ? nn0 : (n > 0 ? n - 1 : 0);
    const int nc1 = v1 ? nn1 : (n > 0 ? n - 1 : 0);
    const int j0 = knn[(size_t)nc0 * 16 + k];
    const int j1 = knn[(size_t)nc1 * 16 + k];

    const float pA0 = p[(size_t)j0 * 3 + 0] - p[(size_t)nc0 * 3 + 0];
    const float pA1 = p[(size_t)j0 * 3 + 1] - p[(size_t)nc0 * 3 + 1];
    const float pA2 = p[(size_t)j0 * 3 + 2] - p[(size_t)nc0 * 3 + 2];
    const float pB0 = p[(size_t)j1 * 3 + 0] - p[(size_t)nc1 * 3 + 0];
    const float pB1 = p[(size_t)j1 * 3 + 1] - p[(size_t)nc1 * 3 + 1];
    const float pB2 = p[(size_t)j1 * 3 + 2] - p[(size_t)nc1 * 3 + 2];
    if (v0 && pr_out) {
        pr_out[((size_t)nn0 * 16 + k) * 3 + 0] = pA0;
        pr_out[((size_t)nn0 * 16 + k) * 3 + 1] = pA1;
        pr_out[((size_t)nn0 * 16 + k) * 3 + 2] = pA2;
    }
    if (v1 && pr_out) {
        pr_out[((size_t)nn1 * 16 + k) * 3 + 0] = pB0;
        pr_out[((size_t)nn1 * 16 + k) * 3 + 1] = pB1;
        pr_out[((size_t)nn1 * 16 + k) * 3 + 2] = pB2;
    }
    if (v0 && knn_out) knn_out[(size_t)nn0 * 16 + k] = (float)j0;
    if (v1 && knn_out) knn_out[(size_t)nn1 * 16 + k] = (float)j1;

    // ---- h = relu(hx[j] + pr @ w01p) ----
    float h0[16], h1[16];
    {
        const float4* hxa = (const float4*)(g_hx + (size_t)j0 * 16);
        const float4* hxb = (const float4*)(g_hx + (size_t)j1 * 16);
#pragma unroll
        for (int o4 = 0; o4 < 4; o4++) {
            float4 a = hxa[o4], b = hxb[o4];
            float4 w0 = *(const float4*)(s_w01p + o4 * 4);
            float4 w1 = *(const float4*)(s_w01p + 16 + o4 * 4);
            float4 w2 = *(const float4*)(s_w01p + 32 + o4 * 4);
            h0[o4 * 4 + 0] = fmaxf(a.x + pA0 * w0.x + pA1 * w1.x + pA2 * w2.x, 0.f);
            h0[o4 * 4 + 1] = fmaxf(a.y + pA0 * w0.y + pA1 * w1.y + pA2 * w2.y, 0.f);
            h0[o4 * 4 + 2] = fmaxf(a.z + pA0 * w0.z + pA1 * w1.z + pA2 * w2.z, 0.f);
            h0[o4 * 4 + 3] = fmaxf(a.w + pA0 * w0.w + pA1 * w1.w + pA2 * w2.w, 0.f);
            h1[o4 * 4 + 0] = fmaxf(b.x + pB0 * w0.x + pB1 * w1.x + pB2 * w2.x, 0.f);
            h1[o4 * 4 + 1] = fmaxf(b.y + pB0 * w0.y + pB1 * w1.y + pB2 * w2.y, 0.f);
            h1[o4 * 4 + 2] = fmaxf(b.z + pB0 * w0.z + pB1 * w1.z + pB2 * w2.z, 0.f);
            h1[o4 * 4 + 3] = fmaxf(b.w + pB0 * w0.w + pB1 * w1.w + pB2 * w2.w, 0.f);
        }
    }

    // ---- symmetrized bilinear, packed over o-pairs ----
    ull e0p[8], e1p[8];
    {
        const ull* bB = (const ull*)s_blB;
#pragma unroll
        for (int q = 0; q < 8; q++) { ull b = bB[q]; e0p[q] = b; e1p[q] = b; }
    }
#pragma unroll
    for (int i = 0; i < 16; i++) {
#pragma unroll
        for (int jj = i; jj < 16; jj++) {
            const ull ga2 = bc2(h0[i] * h0[jj]);
            const ull gb2 = bc2(h1[i] * h1[jj]);
            const ulonglong2* wr = (const ulonglong2*)(s_blS + (i * 16 + jj) * 16);
            ulonglong2 w0 = wr[0], w1 = wr[1], w2 = wr[2], w3 = wr[3];
            e0p[0] = fma2_(ga2, w0.x, e0p[0]); e1p[0] = fma2_(gb2, w0.x, e1p[0]);
            e0p[1] = fma2_(ga2, w0.y, e0p[1]); e1p[1] = fma2_(gb2, w0.y, e1p[1]);
            e0p[2] = fma2_(ga2, w1.x, e0p[2]); e1p[2] = fma2_(gb2, w1.x, e1p[2]);
            e0p[3] = fma2_(ga2, w1.y, e0p[3]); e1p[3] = fma2_(gb2, w1.y, e1p[3]);
            e0p[4] = fma2_(ga2, w2.x, e0p[4]); e1p[4] = fma2_(gb2, w2.x, e1p[4]);
            e0p[5] = fma2_(ga2, w2.y, e0p[5]); e1p[5] = fma2_(gb2, w2.y, e1p[5]);
            e0p[6] = fma2_(ga2, w3.x, e0p[6]); e1p[6] = fma2_(gb2, w3.x, e1p[6]);
            e0p[7] = fma2_(ga2, w3.y, e0p[7]); e1p[7] = fma2_(gb2, w3.y, e1p[7]);
        }
    }
    float e0[16], e1[16];
#pragma unroll
    for (int q = 0; q < 8; q++) {
        upk2(e0p[q], e0[2 * q], e0[2 * q + 1]);
        upk2(e1p[q], e1[2 * q], e1[2 * q + 1]);
    }

    // ---- q vec ----
    float qa[3], qb[3];
#pragma unroll
    for (int d = 0; d < 3; d++) {
        qa[d] = fmaxf(fmaf(pA0, s_lp1f[d], fmaf(pA1, s_lp1f[4 + d], fmaf(pA2, s_lp1f[8 + d], s_lp1c[d]))), 0.f);
        qb[d] = fmaxf(fmaf(pB0, s_lp1f[d], fmaf(pB1, s_lp1f[4 + d], fmaf(pB2, s_lp1f[8 + d], s_lp1c[d]))), 0.f);
    }

    // ---- fused c2a(+q)+BN+relu+c2b, packed ----
    ull hb0p[4], hb1p[4];
#pragma unroll
    for (int m = 0; m < 4; m++) { hb0p[m] = 0ull; hb1p[m] = 0ull; }
#pragma unroll
    for (int cb = 0; cb < 4; cb++) {
        ull a0p[8], a1p[8];
        {
            const ulonglong2* ccp = (const ulonglong2*)(s_c2aC + cb * 16);
            ulonglong2 c0 = ccp[0], c1 = ccp[1], c2 = ccp[2], c3 = ccp[3];
            a0p[0] = c0.x; a0p[1] = c0.y; a0p[2] = c1.x; a0p[3] = c1.y;
            a0p[4] = c2.x; a0p[5] = c2.y; a0p[6] = c3.x; a0p[7] = c3.y;
#pragma unroll
            for (int q = 0; q < 8; q++) a1p[q] = a0p[q];
        }
#pragma unroll
        for (int ei = 0; ei < 16; ei++) {
            const ull va2 = bc2(e0[ei]);
            const ull vb2 = bc2(e1[ei]);
            const ulonglong2* wr = (const ulonglong2*)(s_c2a + ei * 64 + cb * 16);
            ulonglong2 w0 = wr[0], w1 = wr[1], w2 = wr[2], w3 = wr[3];
            a0p[0] = fma2_(va2, w0.x, a0p[0]); a1p[0] = fma2_(vb2, w0.x, a1p[0]);
            a0p[1] = fma2_(va2, w0.y, a0p[1]); a1p[1] = fma2_(vb2, w0.y, a1p[1]);
            a0p[2] = fma2_(va2, w1.x, a0p[2]); a1p[2] = fma2_(vb2, w1.x, a1p[2]);
            a0p[3] = fma2_(va2, w1.y, a0p[3]); a1p[3] = fma2_(vb2, w1.y, a1p[3]);
            a0p[4] = fma2_(va2, w2.x, a0p[4]); a1p[4] = fma2_(vb2, w2.x, a1p[4]);
            a0p[5] = fma2_(va2, w2.y, a0p[5]); a1p[5] = fma2_(vb2, w2.y, a1p[5]);
            a0p[6] = fma2_(va2, w3.x, a0p[6]); a1p[6] = fma2_(vb2, w3.x, a1p[6]);
            a0p[7] = fma2_(va2, w3.y, a0p[7]); a1p[7] = fma2_(vb2, w3.y, a1p[7]);
        }
#pragma unroll
        for (int r = 0; r < 3; r++) {
            const ull va2 = bc2(qa[r]);
            const ull vb2 = bc2(qb[r]);
            const ulonglong2* wr = (const ulonglong2*)(s_c2aQ + r * 64 + cb * 16);
            ulonglong2 w0 = wr[0], w1 = wr[1], w2 = wr[2], w3 = wr[3];
            a0p[0] = fma2_(va2, w0.x, a0p[0]); a1p[0] = fma2_(vb2, w0.x, a1p[0]);
            a0p[1] = fma2_(va2, w0.y, a0p[1]); a1p[1] = fma2_(vb2, w0.y, a1p[1]);
            a0p[2] = fma2_(va2, w1.x, a0p[2]); a1p[2] = fma2_(vb2, w1.x, a1p[2]);
            a0p[3] = fma2_(va2, w1.y, a0p[3]); a1p[3] = fma2_(vb2, w1.y, a1p[3]);
            a0p[4] = fma2_(va2, w2.x, a0p[4]); a1p[4] = fma2_(vb2, w2.x, a1p[4]);
            a0p[5] = fma2_(va2, w2.y, a0p[5]); a1p[5] = fma2_(vb2, w2.y, a1p[5]);
            a0p[6] = fma2_(va2, w3.x, a0p[6]); a1p[6] = fma2_(vb2, w3.x, a1p[6]);
            a0p[7] = fma2_(va2, w3.y, a0p[7]); a1p[7] = fma2_(vb2, w3.y, a1p[7]);
        }
        // BN + relu (scalar) + c2b (packed)
        const ull* scp = (const ull*)(s_bn2as + cb * 16);
        const ull* shp = (const ull*)(s_bn2at + cb * 16);
#pragma unroll
        for (int q = 0; q < 8; q++) {
            float sc0, sc1, sh0, sh1, v00, v01, v10, v11;
            upk2(scp[q], sc0, sc1); upk2(shp[q], sh0, sh1);
            upk2(a0p[q], v00, v01); upk2(a1p[q], v10, v11);
            v00 = fmaxf(fmaf(v00, sc0, sh0), 0.f);
            v01 = fmaxf(fmaf(v01, sc1, sh1), 0.f);
            v10 = fmaxf(fmaf(v10, sc0, sh0), 0.f);
            v11 = fmaxf(fmaf(v11, sc1, sh1), 0.f);
            const ulonglong2* wb0 = (const ulonglong2*)(s_c2b + (cb * 16 + 2 * q) * 8);
            const ulonglong2* wb1 = (const ulonglong2*)(s_c2b + (cb * 16 + 2 * q + 1) * 8);
            ulonglong2 u0 = wb0[0], u1 = wb0[1];
            ulonglong2 u2 = wb1[0], u3 = wb1[1];
            const ull va2 = bc2(v00), vA2 = bc2(v01);
            const ull vb2 = bc2(v10), vB2 = bc2(v11);
            hb0p[0] = fma2_(va2, u0.x, hb0p[0]); hb0p[1] = fma2_(va2, u0.y, hb0p[1]);
            hb0p[2] = fma2_(va2, u1.x, hb0p[2]); hb0p[3] = fma2_(va2, u1.y, hb0p[3]);
            hb0p[0] = fma2_(vA2, u2.x, hb0p[0]); hb0p[1] = fma2_(vA2, u2.y, hb0p[1]);
            hb0p[2] = fma2_(vA2, u3.x, hb0p[2]); hb0p[3] = fma2_(vA2, u3.y, hb0p[3]);
            hb1p[0] = fma2_(vb2, u0.x, hb1p[0]); hb1p[1] = fma2_(vb2, u0.y, hb1p[1]);
            hb1p[2] = fma2_(vb2, u1.x, hb1p[2]); hb1p[3] = fma2_(vb2, u1.y, hb1p[3]);
            hb1p[0] = fma2_(vB2, u2.x, hb1p[0]); hb1p[1] = fma2_(vB2, u2.y, hb1p[1]);
            hb1p[2] = fma2_(vB2, u3.x, hb1p[2]); hb1p[3] = fma2_(vB2, u3.y, hb1p[3]);
        }
    }
    float hbs0[8], hbs1[8];
#pragma unroll
    for (int m = 0; m < 4; m++) {
        upk2(hb0p[m], hbs0[2 * m], hbs0[2 * m + 1]);
        upk2(hb1p[m], hbs1[2 * m], hbs1[2 * m + 1]);
    }
#pragma unroll
    for (int u = 0; u < 8; u++) {
        hbs0[u] = fmaxf(fmaf(hbs0[u], s_bn2bs[u], s_bn2bt[u]), 0.f);
        hbs1[u] = fmaxf(fmaf(hbs1[u], s_bn2bs[u], s_bn2bt[u]), 0.f);
    }

    // ---- logits (packed) ----
    ull lg0p[4], lg1p[4];
    {
        const ull* cbp = (const ull*)s_c2cb;
#pragma unroll
        for (int m = 0; m < 4; m++) { ull b = cbp[m]; lg0p[m] = b; lg1p[m] = b; }
    }
#pragma unroll
    for (int u = 0; u < 8; u++) {
        const ull h02 = bc2(hbs0[u]);
        const ull h12 = bc2(hbs1[u]);
        const ulonglong2* wr = (const ulonglong2*)(s_c2c + u * 8);
        ulonglong2 w0 = wr[0], w1 = wr[1];
        lg0p[0] = fma2_(h02, w0.x, lg0p[0]); lg1p[0] = fma2_(h12, w0.x, lg1p[0]);
        lg0p[1] = fma2_(h02, w0.y, lg0p[1]); lg1p[1] = fma2_(h12, w0.y, lg1p[1]);
        lg0p[2] = fma2_(h02, w1.x, lg0p[2]); lg1p[2] = fma2_(h12, w1.x, lg1p[2]);
        lg0p[3] = fma2_(h02, w1.y, lg0p[3]); lg1p[3] = fma2_(h12, w1.y, lg1p[3]);
    }
    float lg0[8], lg1[8];
#pragma unroll
    for (int m = 0; m < 4; m++) {
        upk2(lg0p[m], lg0[2 * m], lg0[2 * m + 1]);
        upk2(lg1p[m], lg1[2 * m], lg1[2 * m + 1]);
    }

    // ---- softmax over 16 k-lanes ----
    float ws0[8], ws1[8];
#pragma unroll
    for (int c = 0; c < 8; c++) {
        float m0 = lg0[c], m1 = lg1[c];
#pragma unroll
        for (int d = 8; d > 0; d >>= 1) {
            m0 = fmaxf(m0, __shfl_xor_sync(0xffffffffu, m0, d));
            m1 = fmaxf(m1, __shfl_xor_sync(0xffffffffu, m1, d));
        }
        float x0 = __expf(lg0[c] - m0);
        float x1 = __expf(lg1[c] - m1);
        float s0 = x0, s1 = x1;
#pragma unroll
        for (int d = 8; d > 0; d >>= 1) {
            s0 += __shfl_xor_sync(0xffffffffu, s0, d);
            s1 += __shfl_xor_sync(0xffffffffu, s1, d);
        }
        ws0[c] = x0 / s0;
        ws1[c] = x1 / s1;
    }
    ull ws0p[4], ws1p[4];
#pragma unroll
    for (int m = 0; m < 4; m++) {
        ws0p[m] = pk2(ws0[2 * m], ws0[2 * m + 1]);
        ws1p[m] = pk2(ws1[2 * m], ws1[2 * m + 1]);
    }

    // ---- epilogue (packed): xk = (y + pe) * w ; out = sum_k ----
    {
        const float* yr0 = g_y + (size_t)j0 * 64;
        const float* yr1 = g_y + (size_t)j1 * 64;
        float* xp0 = (v0 && xk_out) ? (xk_out + ((size_t)nn0 * 16 + k) * 64) : nullptr;
        float* xp1 = (v1 && xk_out) ? (xk_out + ((size_t)nn1 * 16 + k) * 64) : nullptr;
        const ull qa0 = bc2(qa[0]), qa1 = bc2(qa[1]), qa2v = bc2(qa[2]);
        const ull qb0 = bc2(qb[0]), qb1 = bc2(qb[1]), qb2v = bc2(qb[2]);
#pragma unroll
        for (int c4 = 0; c4 < 16; c4++) {
            ulonglong2 l0 = ((const ulonglong2*)s_lp2)[c4];
            ulonglong2 l1 = ((const ulonglong2*)(s_lp2 + 64))[c4];
            ulonglong2 l2 = ((const ulonglong2*)(s_lp2 + 128))[c4];
            ulonglong2 lb = ((const ulonglong2*)s_lp2b)[c4];
            ulonglong2 y0 = ((const ulonglong2*)yr0)[c4];
            ulonglong2 y1 = ((const ulonglong2*)yr1)[c4];
            const ull wA0 = ws0p[(2 * c4) & 3], wA1 = ws0p[(2 * c4 + 1) & 3];
            const ull wB0 = ws1p[(2 * c4) & 3], wB1 = ws1p[(2 * c4 + 1) & 3];
            ull pe;
            pe = fma2_(qa0, l0.x, fma2_(qa1, l1.x, fma2_(qa2v, l2.x, lb.x)));
            ull v0x = mul2_(add2_(y0.x, pe), wA0);
            pe = fma2_(qa0, l0.y, fma2_(qa1, l1.y, fma2_(qa2v, l2.y, lb.y)));
            ull v0y = mul2_(add2_(y0.y, pe), wA1);
            pe = fma2_(qb0, l0.x, fma2_(qb1, l1.x, fma2_(qb2v, l2.x, lb.x)));
            ull v1x = mul2_(add2_(y1.x, pe), wB0);
            pe = fma2_(qb0, l0.y, fma2_(qb1, l1.y, fma2_(qb2v, l2.y, lb.y)));
            ull v1y = mul2_(add2_(y1.y, pe), wB1);
            if (xp0) { ulonglong2 t; t.x = v0x; t.y = v0y; ((ulonglong2*)xp0)[c4] = t; }
            if (xp1) { ulonglong2 t; t.x = v1x; t.y = v1y; ((ulonglong2*)xp1)[c4] = t; }
#pragma unroll
            for (int d = 8; d > 0; d >>= 1) {
                v0x = add2_(v0x, __shfl_down_sync(0xffffffffu, v0x, d, 16));
                v0y = add2_(v0y, __shfl_down_sync(0xffffffffu, v0y, d, 16));
                v1x = add2_(v1x, __shfl_down_sync(0xffffffffu, v1x, d, 16));
                v1y = add2_(v1y, __shfl_down_sync(0xffffffffu, v1y, d, 16));
            }
            if (k == 0) {
                if (v0) { ulonglong2 t; t.x = v0x; t.y = v0y; ((ulonglong2*)(out + (size_t)nn0 * 64))[c4] = t; }
                if (v1) { ulonglong2 t; t.x = v1x; t.y = v1y; ((ulonglong2*)(out + (size_t)nn1 * 64))[c4] = t; }
            }
        }
    }
}

// ---------------------------------------------------------------------------
extern "C" void kernel_launch(void* const* d_in, const int* in_sizes, int n_in,
                              void* d_out, int out_size)
{
    const float* p    = (const float*)d_in[0];
    const float* x    = (const float*)d_in[1];
    const int*   knn  = (const int*)d_in[2];
    const float* w01  = (const float*)d_in[3];
    const float* b01  = (const float*)d_in[4];
    const float* blW  = (const float*)d_in[5];
    const float* blB  = (const float*)d_in[6];
    const float* lp1w = (const float*)d_in[7];
    const float* lp1b = (const float*)d_in[8];
    const float* bnpg = (const float*)d_in[9];
    const float* bnpb = (const float*)d_in[10];
    const float* bnpm = (const float*)d_in[11];
    const float* bnpv = (const float*)d_in[12];
    const float* lp2w = (const float*)d_in[13];
    const float* lp2b = (const float*)d_in[14];
    const float* c2aw = (const float*)d_in[15];
    const float* bn2ag = (const float*)d_in[16];
    const float* bn2ab = (const float*)d_in[17];
    const float* bn2am = (const float*)d_in[18];
    const float* bn2av = (const float*)d_in[19];
    const float* c2bw  = (const float*)d_in[20];
    const float* bn2bg = (const float*)d_in[21];
    const float* bn2bb = (const float*)d_in[22];
    const float* bn2bm = (const float*)d_in[23];
    const float* bn2bv = (const float*)d_in[24];
    const float* c2cw  = (const float*)d_in[25];
    const float* c2cb  = (const float*)d_in[26];
    const float* w03   = (const float*)d_in[27];
    const float* b03   = (const float*)d_in[28];

    const int n = in_sizes[0] / 3;
    float* out = (float*)d_out;

    const long long total = (long long)n * 64 + (long long)n * 16 * 64 +
                            (long long)n * 16 + (long long)n * 16 * 3;
    float* xk_out = nullptr;
    float* knn_out = nullptr;
    float* pr_out = nullptr;
    if ((long long)out_size >= total) {
        xk_out  = out + (size_t)n * 64;
        knn_out = xk_out + (size_t)n * 16 * 64;
        pr_out  = knn_out + (size_t)n * 16;
    }

    setup_kernel<<<17, 256>>>(blW, c2aw, lp2w, lp2b);
    prep_kernel<<<(n + 31) / 32, 256>>>(x, w03, b03, w01, b01, n);
    pm_main_kernel<<<(n + 31) / 32, 256>>>(p, knn, w01, blB,
                               lp1w, lp1b, bnpg, bnpb, bnpm, bnpv, lp2w, lp2b,
                               c2aw, bn2ag, bn2ab, bn2am, bn2av,
                               c2bw, bn2bg, bn2bb, bn2bm, bn2bv,
                               c2cw, c2cb,
                               out, xk_out, knn_out, pr_out, n);
}